// round 6
// baseline (speedup 1.0000x reference)
#include <cuda_runtime.h>
#include <cuda_fp16.h>
#include <cstdint>

#define SEQ 4096
#define DIM 768
#define NHEAD 12
#define DHEAD 64
#define POST_SCALE 19.595917942265423f  // sqrt(384)

// ---- device scratch (allocation-free rule) ----
__device__ __half g_x16[SEQ * DIM];
__device__ __half g_w[4 * DIM * DIM];          // packed Wq,Wk,Wv,Wo (fp16)
__device__ float  g_bqkv[3 * DIM];             // packed bq,bk,bv
__device__ __half g_QKV[3 * SEQ * DIM];        // Q,K,V planes (fp16)
__device__ __half g_Ah[SEQ * DIM];
__device__ float  g_z[(size_t)SEQ * SEQ];      // 64 MB  softmax denominators
__device__ __half g_P[(size_t)NHEAD * SEQ * SEQ];  // 402 MB

// ---------------- PTX helpers ----------------
__device__ __forceinline__ void cp16(uint32_t dst, const void* src) {
    asm volatile("cp.async.cg.shared.global [%0], [%1], 16;\n" :: "r"(dst), "l"(src));
}
#define CP_COMMIT() asm volatile("cp.async.commit_group;\n")
#define CP_WAIT0()  asm volatile("cp.async.wait_group 0;\n")
#define CP_WAIT1()  asm volatile("cp.async.wait_group 1;\n")
#define CP_WAIT2()  asm volatile("cp.async.wait_group 2;\n")

#define LDSM4(R, a) asm volatile( \
    "ldmatrix.sync.aligned.m8n8.x4.shared.b16 {%0,%1,%2,%3}, [%4];" \
    : "=r"((R)[0]), "=r"((R)[1]), "=r"((R)[2]), "=r"((R)[3]) : "r"(a))
#define LDSM4T(R, a) asm volatile( \
    "ldmatrix.sync.aligned.m8n8.x4.trans.shared.b16 {%0,%1,%2,%3}, [%4];" \
    : "=r"((R)[0]), "=r"((R)[1]), "=r"((R)[2]), "=r"((R)[3]) : "r"(a))

__device__ __forceinline__ void mma16(float* c, const uint32_t* a, const uint32_t* b) {
    asm volatile(
        "mma.sync.aligned.m16n8k16.row.col.f32.f16.f16.f32 "
        "{%0,%1,%2,%3},{%4,%5,%6,%7},{%8,%9},{%0,%1,%2,%3};\n"
        : "+f"(c[0]), "+f"(c[1]), "+f"(c[2]), "+f"(c[3])
        : "r"(a[0]), "r"(a[1]), "r"(a[2]), "r"(a[3]), "r"(b[0]), "r"(b[1]));
}

// swizzled byte offset within a tile of 128B rows (8x16B chunks, chunk ^= row&7)
__device__ __forceinline__ uint32_t swz(int row, int ch) {
    return (uint32_t)(row * 128 + ((ch ^ (row & 7)) << 4));
}

// ---------------- merged fp32 -> fp16 convert + packing ----------------
#define NX2 (SEQ * DIM / 2)
#define NW2 (DIM * DIM / 2)
__global__ void cvt_all(
    const float* __restrict__ x,
    const float* __restrict__ Wq, const float* __restrict__ Wk,
    const float* __restrict__ Wv, const float* __restrict__ Wo,
    const float* __restrict__ bq, const float* __restrict__ bk,
    const float* __restrict__ bv,
    __half* __restrict__ x16, __half* __restrict__ wpk,
    float* __restrict__ bqkv)
{
    int i = blockIdx.x * blockDim.x + threadIdx.x;
    int stride = gridDim.x * blockDim.x;
    if (i < 3 * DIM) {
        bqkv[i] = (i < DIM) ? bq[i] : (i < 2 * DIM ? bk[i - DIM] : bv[i - 2 * DIM]);
    }
    __half2* xd = (__half2*)x16;
    __half2* wd = (__half2*)wpk;
    for (int j = i; j < NX2 + 4 * NW2; j += stride) {
        float2 v;
        if (j < NX2) {
            v = ((const float2*)x)[j];
            xd[j] = __floats2half2_rn(v.x, v.y);
        } else {
            int k = j - NX2;
            int seg = k / NW2, off = k - seg * NW2;
            const float* W = (seg == 0) ? Wq : (seg == 1) ? Wk : (seg == 2) ? Wv : Wo;
            v = ((const float2*)W)[off];
            wd[k] = __floats2half2_rn(v.x, v.y);
        }
    }
}

// ============================================================
// QKV fused: Y[plane][4096,768] = X @ Wpk[n,:]^T + bqkv.
// ============================================================
__global__ __launch_bounds__(256) void qkv16(
    const __half* __restrict__ X, const __half* __restrict__ W,
    const float* __restrict__ bias, __half* __restrict__ QKV)
{
    __shared__ __align__(16) unsigned char smbuf[49152];
    const uint32_t smb = (uint32_t)__cvta_generic_to_shared(smbuf);
    const int tid = threadIdx.x, lane = tid & 31, warp = tid >> 5;
    const int wm = warp >> 1, wn = warp & 1;
    const int m0 = blockIdx.y * 128, n0 = blockIdx.x * 64;
    const int g = lane >> 2, t4 = lane & 3;
    const int plane = n0 / DIM, ncol = n0 - plane * DIM;
    __half* Y = QKV + (size_t)plane * SEQ * DIM;

    float c[2][4][4];
#pragma unroll
    for (int mt = 0; mt < 2; mt++)
#pragma unroll
        for (int nt = 0; nt < 4; nt++)
#pragma unroll
            for (int r = 0; r < 4; r++) c[mt][nt][r] = 0.f;

    {
        uint32_t ab = smb, bb = smb + 16384;
#pragma unroll
        for (int i = 0; i < 4; i++) {
            int op = tid + i * 256; int row = op >> 3, ch = op & 7;
            cp16(ab + swz(row, ch), X + (size_t)(m0 + row) * DIM + ch * 8);
        }
#pragma unroll
        for (int i = 0; i < 2; i++) {
            int op = tid + i * 256; int row = op >> 3, ch = op & 7;
            cp16(bb + swz(row, ch), W + (size_t)(n0 + row) * DIM + ch * 8);
        }
        CP_COMMIT();
    }

    for (int it = 0; it < 12; it++) {
        if (it < 11) {
            int kt = (it + 1) * 64;
            uint32_t ab = smb + ((it + 1) & 1) * 24576, bb = ab + 16384;
#pragma unroll
            for (int i = 0; i < 4; i++) {
                int op = tid + i * 256; int row = op >> 3, ch = op & 7;
                cp16(ab + swz(row, ch), X + (size_t)(m0 + row) * DIM + kt + ch * 8);
            }
#pragma unroll
            for (int i = 0; i < 2; i++) {
                int op = tid + i * 256; int row = op >> 3, ch = op & 7;
                cp16(bb + swz(row, ch), W + (size_t)(n0 + row) * DIM + kt + ch * 8);
            }
            CP_COMMIT();
            CP_WAIT1();
        } else {
            CP_WAIT0();
        }
        __syncthreads();

        uint32_t ab = smb + (it & 1) * 24576, bb = ab + 16384;
#pragma unroll
        for (int ks = 0; ks < 4; ks++) {
            uint32_t a[2][4], b[2][4];
#pragma unroll
            for (int mt = 0; mt < 2; mt++) {
                int row = wm * 32 + mt * 16 + (lane & 15);
                int ch = ks * 2 + (lane >> 4);
                LDSM4(a[mt], ab + swz(row, ch));
            }
#pragma unroll
            for (int p = 0; p < 2; p++) {
                int row = wn * 32 + p * 16 + (lane & 7) + ((lane >> 4) << 3);
                int ch = ks * 2 + ((lane >> 3) & 1);
                LDSM4(b[p], bb + swz(row, ch));
            }
#pragma unroll
            for (int mt = 0; mt < 2; mt++) {
                mma16(c[mt][0], a[mt], &b[0][0]);
                mma16(c[mt][1], a[mt], &b[0][2]);
                mma16(c[mt][2], a[mt], &b[1][0]);
                mma16(c[mt][3], a[mt], &b[1][2]);
            }
        }
        __syncthreads();
    }

#pragma unroll
    for (int mt = 0; mt < 2; mt++)
#pragma unroll
        for (int nt = 0; nt < 4; nt++) {
            int cg = n0 + wn * 32 + nt * 8 + t4 * 2;
            float b0 = bias[cg], b1 = bias[cg + 1];
            int col = ncol + wn * 32 + nt * 8 + t4 * 2;
#pragma unroll
            for (int rh = 0; rh < 2; rh++) {
                int row = m0 + wm * 32 + mt * 16 + g + rh * 8;
                *(__half2*)(Y + (size_t)row * DIM + col) =
                    __floats2half2_rn(c[mt][nt][rh * 2] + b0, c[mt][nt][rh * 2 + 1] + b1);
            }
        }
}

// ============================================================
// Final linear: out[4096,768] fp32 = A @ Wo^T + bo.
// ============================================================
__global__ __launch_bounds__(256) void oproj16(
    const __half* __restrict__ X, const __half* __restrict__ W,
    const float* __restrict__ bias, float* __restrict__ Y)
{
    __shared__ __align__(16) unsigned char smbuf[49152];
    const uint32_t smb = (uint32_t)__cvta_generic_to_shared(smbuf);
    const int tid = threadIdx.x, lane = tid & 31, warp = tid >> 5;
    const int wm = warp >> 1, wn = warp & 1;
    const int m0 = blockIdx.y * 128, n0 = blockIdx.x * 64;
    const int g = lane >> 2, t4 = lane & 3;

    float c[2][4][4];
#pragma unroll
    for (int mt = 0; mt < 2; mt++)
#pragma unroll
        for (int nt = 0; nt < 4; nt++)
#pragma unroll
            for (int r = 0; r < 4; r++) c[mt][nt][r] = 0.f;

    {
        uint32_t ab = smb, bb = smb + 16384;
#pragma unroll
        for (int i = 0; i < 4; i++) {
            int op = tid + i * 256; int row = op >> 3, ch = op & 7;
            cp16(ab + swz(row, ch), X + (size_t)(m0 + row) * DIM + ch * 8);
        }
#pragma unroll
        for (int i = 0; i < 2; i++) {
            int op = tid + i * 256; int row = op >> 3, ch = op & 7;
            cp16(bb + swz(row, ch), W + (size_t)(n0 + row) * DIM + ch * 8);
        }
        CP_COMMIT();
    }

    for (int it = 0; it < 12; it++) {
        if (it < 11) {
            int kt = (it + 1) * 64;
            uint32_t ab = smb + ((it + 1) & 1) * 24576, bb = ab + 16384;
#pragma unroll
            for (int i = 0; i < 4; i++) {
                int op = tid + i * 256; int row = op >> 3, ch = op & 7;
                cp16(ab + swz(row, ch), X + (size_t)(m0 + row) * DIM + kt + ch * 8);
            }
#pragma unroll
            for (int i = 0; i < 2; i++) {
                int op = tid + i * 256; int row = op >> 3, ch = op & 7;
                cp16(bb + swz(row, ch), W + (size_t)(n0 + row) * DIM + kt + ch * 8);
            }
            CP_COMMIT();
            CP_WAIT1();
        } else {
            CP_WAIT0();
        }
        __syncthreads();

        uint32_t ab = smb + (it & 1) * 24576, bb = ab + 16384;
#pragma unroll
        for (int ks = 0; ks < 4; ks++) {
            uint32_t a[2][4], b[2][4];
#pragma unroll
            for (int mt = 0; mt < 2; mt++) {
                int row = wm * 32 + mt * 16 + (lane & 15);
                int ch = ks * 2 + (lane >> 4);
                LDSM4(a[mt], ab + swz(row, ch));
            }
#pragma unroll
            for (int p = 0; p < 2; p++) {
                int row = wn * 32 + p * 16 + (lane & 7) + ((lane >> 4) << 3);
                int ch = ks * 2 + ((lane >> 3) & 1);
                LDSM4(b[p], bb + swz(row, ch));
            }
#pragma unroll
            for (int mt = 0; mt < 2; mt++) {
                mma16(c[mt][0], a[mt], &b[0][0]);
                mma16(c[mt][1], a[mt], &b[0][2]);
                mma16(c[mt][2], a[mt], &b[1][0]);
                mma16(c[mt][3], a[mt], &b[1][2]);
            }
        }
        __syncthreads();
    }

#pragma unroll
    for (int mt = 0; mt < 2; mt++)
#pragma unroll
        for (int nt = 0; nt < 4; nt++) {
            int col = n0 + wn * 32 + nt * 8 + t4 * 2;
            float b0 = bias[col], b1 = bias[col + 1];
#pragma unroll
            for (int rh = 0; rh < 2; rh++) {
                int row = m0 + wm * 32 + mt * 16 + g + rh * 8;
                float2 v = {c[mt][nt][rh * 2] + b0, c[mt][nt][rh * 2 + 1] + b1};
                *(float2*)(Y + (size_t)row * DIM + col) = v;
            }
        }
}

// ============================================================
// Two-pass head-softmax attention scores.
// Tile: 128(s) x 64(t), 512 threads, 16 warps (4m x 4n),
// warp tile 32(m) x 16(n). K tile 16KB + Q tile 8KB per stage.
// zpass: z[s,t] = sum_h exp(score_h)      (z in registers)
// ppass: P[h,s,t] = exp(score_h)*scale/z  (smem-staged stores)
// ============================================================
#define SP_STAGE 24576                  // 16KB K + 8KB Q
#define Z_SMEM   (2 * SP_STAGE)         // 48KB
#define PSTG_OFF (2 * SP_STAGE)
#define P_SMEM   (2 * SP_STAGE + 128 * 144)  // + 18KB P stage

__global__ __launch_bounds__(512, 2) void zpass(
    const __half* __restrict__ Qh, const __half* __restrict__ Kh,
    float* __restrict__ z)
{
    extern __shared__ __align__(16) unsigned char sm[];
    const uint32_t smb = (uint32_t)__cvta_generic_to_shared(sm);
    const int tid = threadIdx.x, lane = tid & 31, warp = tid >> 5;
    const int wm = warp >> 2, wn = warp & 3;
    const int s0 = blockIdx.y * 128, t0 = blockIdx.x * 64;
    const int g = lane >> 2, t4 = lane & 3;

    float zacc[2][2][4];
#pragma unroll
    for (int mt = 0; mt < 2; mt++)
#pragma unroll
        for (int nt = 0; nt < 2; nt++)
#pragma unroll
            for (int r = 0; r < 4; r++) zacc[mt][nt][r] = 0.f;

    // prologue: head 0 into buf 0
#pragma unroll
    for (int i = 0; i < 3; i++) {
        int op = tid + i * 512;
        if (op < 1024) {
            int row = op >> 3, ch = op & 7;
            cp16(smb + swz(row, ch), Kh + (size_t)(s0 + row) * DIM + ch * 8);
        } else {
            int q = op - 1024; int row = q >> 3, ch = q & 7;
            cp16(smb + 16384 + swz(row, ch), Qh + (size_t)(t0 + row) * DIM + ch * 8);
        }
    }
    CP_COMMIT();

    for (int h = 0; h < NHEAD; h++) {
        if (h < NHEAD - 1) {
            uint32_t base = smb + ((h + 1) & 1) * SP_STAGE;
            int hc = (h + 1) * DHEAD;
#pragma unroll
            for (int i = 0; i < 3; i++) {
                int op = tid + i * 512;
                if (op < 1024) {
                    int row = op >> 3, ch = op & 7;
                    cp16(base + swz(row, ch), Kh + (size_t)(s0 + row) * DIM + hc + ch * 8);
                } else {
                    int q = op - 1024; int row = q >> 3, ch = q & 7;
                    cp16(base + 16384 + swz(row, ch), Qh + (size_t)(t0 + row) * DIM + hc + ch * 8);
                }
            }
            CP_COMMIT();
            CP_WAIT1();
        } else {
            CP_WAIT0();
        }
        __syncthreads();

        uint32_t kb = smb + (h & 1) * SP_STAGE, qb = kb + 16384;
        float acc[2][2][4];
#pragma unroll
        for (int mt = 0; mt < 2; mt++)
#pragma unroll
            for (int nt = 0; nt < 2; nt++)
#pragma unroll
                for (int r = 0; r < 4; r++) acc[mt][nt][r] = 0.f;

#pragma unroll
        for (int ks = 0; ks < 4; ks++) {
            uint32_t a[2][4], b[4];
#pragma unroll
            for (int mt = 0; mt < 2; mt++) {
                int row = wm * 32 + mt * 16 + (lane & 15);
                int ch = ks * 2 + (lane >> 4);
                LDSM4(a[mt], kb + swz(row, ch));
            }
            {
                int row = wn * 16 + (lane & 7) + ((lane >> 4) << 3);
                int ch = ks * 2 + ((lane >> 3) & 1);
                LDSM4(b, qb + swz(row, ch));
            }
#pragma unroll
            for (int mt = 0; mt < 2; mt++) {
                mma16(acc[mt][0], a[mt], &b[0]);
                mma16(acc[mt][1], a[mt], &b[2]);
            }
        }
#pragma unroll
        for (int mt = 0; mt < 2; mt++)
#pragma unroll
            for (int nt = 0; nt < 2; nt++)
#pragma unroll
                for (int r = 0; r < 4; r++)
                    zacc[mt][nt][r] += __expf(acc[mt][nt][r]);
        __syncthreads();
    }

#pragma unroll
    for (int mt = 0; mt < 2; mt++)
#pragma unroll
        for (int nt = 0; nt < 2; nt++) {
            int col = t0 + wn * 16 + nt * 8 + t4 * 2;
#pragma unroll
            for (int rh = 0; rh < 2; rh++) {
                int row = s0 + wm * 32 + mt * 16 + g + rh * 8;
                float2 v = {zacc[mt][nt][rh * 2], zacc[mt][nt][rh * 2 + 1]};
                *(float2*)&z[(size_t)row * SEQ + col] = v;
            }
        }
}

__global__ __launch_bounds__(512, 2) void ppass(
    const __half* __restrict__ Qh, const __half* __restrict__ Kh,
    const float* __restrict__ z, __half* __restrict__ P)
{
    extern __shared__ __align__(16) unsigned char sm[];
    const uint32_t smb = (uint32_t)__cvta_generic_to_shared(sm);
    __half* sp = (__half*)(sm + PSTG_OFF);   // 128 rows x 144B stride
    const int tid = threadIdx.x, lane = tid & 31, warp = tid >> 5;
    const int wm = warp >> 2, wn = warp & 3;
    const int s0 = blockIdx.y * 128, t0 = blockIdx.x * 64;
    const int g = lane >> 2, t4 = lane & 3;

    // load reciprocal z (with POST_SCALE folded) for this thread's cells
    float rz[2][2][4];
#pragma unroll
    for (int mt = 0; mt < 2; mt++)
#pragma unroll
        for (int nt = 0; nt < 2; nt++) {
            int col = t0 + wn * 16 + nt * 8 + t4 * 2;
#pragma unroll
            for (int rh = 0; rh < 2; rh++) {
                int row = s0 + wm * 32 + mt * 16 + g + rh * 8;
                float2 v = *(const float2*)&z[(size_t)row * SEQ + col];
                rz[mt][nt][rh * 2]     = POST_SCALE / v.x;
                rz[mt][nt][rh * 2 + 1] = POST_SCALE / v.y;
            }
        }

    // prologue: head 0 into buf 0
#pragma unroll
    for (int i = 0; i < 3; i++) {
        int op = tid + i * 512;
        if (op < 1024) {
            int row = op >> 3, ch = op & 7;
            cp16(smb + swz(row, ch), Kh + (size_t)(s0 + row) * DIM + ch * 8);
        } else {
            int q = op - 1024; int row = q >> 3, ch = q & 7;
            cp16(smb + 16384 + swz(row, ch), Qh + (size_t)(t0 + row) * DIM + ch * 8);
        }
    }
    CP_COMMIT();

    for (int h = 0; h < NHEAD; h++) {
        if (h < NHEAD - 1) {
            uint32_t base = smb + ((h + 1) & 1) * SP_STAGE;
            int hc = (h + 1) * DHEAD;
#pragma unroll
            for (int i = 0; i < 3; i++) {
                int op = tid + i * 512;
                if (op < 1024) {
                    int row = op >> 3, ch = op & 7;
                    cp16(base + swz(row, ch), Kh + (size_t)(s0 + row) * DIM + hc + ch * 8);
                } else {
                    int q = op - 1024; int row = q >> 3, ch = q & 7;
                    cp16(base + 16384 + swz(row, ch), Qh + (size_t)(t0 + row) * DIM + hc + ch * 8);
                }
            }
            CP_COMMIT();
            CP_WAIT1();
        } else {
            CP_WAIT0();
        }
        __syncthreads();

        uint32_t kb = smb + (h & 1) * SP_STAGE, qb = kb + 16384;
        float acc[2][2][4];
#pragma unroll
        for (int mt = 0; mt < 2; mt++)
#pragma unroll
            for (int nt = 0; nt < 2; nt++)
#pragma unroll
                for (int r = 0; r < 4; r++) acc[mt][nt][r] = 0.f;

#pragma unroll
        for (int ks = 0; ks < 4; ks++) {
            uint32_t a[2][4], b[4];
#pragma unroll
            for (int mt = 0; mt < 2; mt++) {
                int row = wm * 32 + mt * 16 + (lane & 15);
                int ch = ks * 2 + (lane >> 4);
                LDSM4(a[mt], kb + swz(row, ch));
            }
            {
                int row = wn * 16 + (lane & 7) + ((lane >> 4) << 3);
                int ch = ks * 2 + ((lane >> 3) & 1);
                LDSM4(b, qb + swz(row, ch));
            }
#pragma unroll
            for (int mt = 0; mt < 2; mt++) {
                mma16(acc[mt][0], a[mt], &b[0]);
                mma16(acc[mt][1], a[mt], &b[2]);
            }
        }

        // stage P tile (padded stride 144B) for coalesced stores
#pragma unroll
        for (int mt = 0; mt < 2; mt++)
#pragma unroll
            for (int nt = 0; nt < 2; nt++) {
                int c = wn * 16 + nt * 8 + t4 * 2;
#pragma unroll
                for (int rh = 0; rh < 2; rh++) {
                    int r = wm * 32 + mt * 16 + g + rh * 8;
                    *(__half2*)((unsigned char*)sp + r * 144 + c * 2) =
                        __floats2half2_rn(
                            __expf(acc[mt][nt][rh * 2]) * rz[mt][nt][rh * 2],
                            __expf(acc[mt][nt][rh * 2 + 1]) * rz[mt][nt][rh * 2 + 1]);
                }
            }
        __syncthreads();

        // coalesced 16B stores: 128 rows x 8 chunks
#pragma unroll
        for (int i = 0; i < 2; i++) {
            int op = tid + i * 512;
            int row = op >> 3, seg = op & 7;
            uint4 v = *(const uint4*)((unsigned char*)sp + row * 144 + seg * 16);
            *(uint4*)(P + ((size_t)h * SEQ + s0 + row) * SEQ + t0 + seg * 8) = v;
        }
        __syncthreads();
    }
}

// ============================================================
// PV: out[s, h*64+d] = sum_t P[h,s,t] * V[t, h*64+d], fp16 out.
// BM=128, BN=64, BK=64, 3-stage cp.async ring, 256 threads.
// ============================================================
#define PV_STAGE 24576    // 16KB A + 8KB B per stage
#define PV_SMEM  (3 * PV_STAGE)

__global__ __launch_bounds__(256) void pv16(
    const __half* __restrict__ P, const __half* __restrict__ V,
    __half* __restrict__ Y)
{
    extern __shared__ __align__(16) unsigned char pvsm[];
    const uint32_t smb = (uint32_t)__cvta_generic_to_shared(pvsm);
    const int tid = threadIdx.x, lane = tid & 31, warp = tid >> 5;
    const int wm = warp >> 1, wn = warp & 1;
    const int h = blockIdx.z;
    const int m0 = blockIdx.y * 128;
    const int g = lane >> 2, t4 = lane & 3;
    const __half* Ph = P + (size_t)h * SEQ * SEQ;

    float c[2][4][4];
#pragma unroll
    for (int mt = 0; mt < 2; mt++)
#pragma unroll
        for (int nt = 0; nt < 4; nt++)
#pragma unroll
            for (int r = 0; r < 4; r++) c[mt][nt][r] = 0.f;

#pragma unroll
    for (int st = 0; st < 2; st++) {
        int kt = st * 64;
        uint32_t ab = smb + st * PV_STAGE, bb = ab + 16384;
#pragma unroll
        for (int i = 0; i < 4; i++) {
            int op = tid + i * 256; int row = op >> 3, ch = op & 7;
            cp16(ab + swz(row, ch), Ph + (size_t)(m0 + row) * SEQ + kt + ch * 8);
        }
#pragma unroll
        for (int i = 0; i < 2; i++) {
            int op = tid + i * 256; int row = op >> 3, ch = op & 7;
            cp16(bb + swz(row, ch), V + (size_t)(kt + row) * DIM + h * DHEAD + ch * 8);
        }
        CP_COMMIT();
    }

    for (int it = 0; it < 64; it++) {
        int left = 63 - it;
        if (left >= 2) {
            int kt = (it + 2) * 64;
            uint32_t ab = smb + ((it + 2) % 3) * PV_STAGE, bb = ab + 16384;
#pragma unroll
            for (int i = 0; i < 4; i++) {
                int op = tid + i * 256; int row = op >> 3, ch = op & 7;
                cp16(ab + swz(row, ch), Ph + (size_t)(m0 + row) * SEQ + kt + ch * 8);
            }
#pragma unroll
            for (int i = 0; i < 2; i++) {
                int op = tid + i * 256; int row = op >> 3, ch = op & 7;
                cp16(bb + swz(row, ch), V + (size_t)(kt + row) * DIM + h * DHEAD + ch * 8);
            }
            CP_COMMIT();
            CP_WAIT2();
        } else if (left == 1) {
            CP_WAIT1();
        } else {
            CP_WAIT0();
        }
        __syncthreads();

        uint32_t ab = smb + (it % 3) * PV_STAGE, bb = ab + 16384;
#pragma unroll
        for (int ks = 0; ks < 4; ks++) {
            uint32_t a[2][4], b[2][4];
#pragma unroll
            for (int mt = 0; mt < 2; mt++) {
                int row = wm * 32 + mt * 16 + (lane & 15);
                int ch = ks * 2 + (lane >> 4);
                LDSM4(a[mt], ab + swz(row, ch));
            }
#pragma unroll
            for (int p = 0; p < 2; p++) {
                int row = ks * 16 + (lane & 15);
                int ch = wn * 4 + p * 2 + (lane >> 4);
                LDSM4T(b[p], bb + swz(row, ch));
            }
#pragma unroll
            for (int mt = 0; mt < 2; mt++) {
                mma16(c[mt][0], a[mt], &b[0][0]);
                mma16(c[mt][1], a[mt], &b[0][2]);
                mma16(c[mt][2], a[mt], &b[1][0]);
                mma16(c[mt][3], a[mt], &b[1][2]);
            }
        }
        __syncthreads();
    }

#pragma unroll
    for (int mt = 0; mt < 2; mt++)
#pragma unroll
        for (int nt = 0; nt < 4; nt++) {
            int col = h * DHEAD + wn * 32 + nt * 8 + t4 * 2;
#pragma unroll
            for (int rh = 0; rh < 2; rh++) {
                int row = m0 + wm * 32 + mt * 16 + g + rh * 8;
                *(__half2*)(Y + (size_t)row * DIM + col) =
                    __floats2half2_rn(c[mt][nt][rh * 2], c[mt][nt][rh * 2 + 1]);
            }
        }
}

// ============================================================
extern "C" void kernel_launch(void* const* d_in, const int* in_sizes, int n_in,
                              void* d_out, int out_size)
{
    const float* x  = (const float*)d_in[0];
    const float* Wq = (const float*)d_in[1];
    const float* bq = (const float*)d_in[2];
    const float* Wk = (const float*)d_in[3];
    const float* bk = (const float*)d_in[4];
    const float* Wv = (const float*)d_in[5];
    const float* bv = (const float*)d_in[6];
    const float* Wo = (const float*)d_in[7];
    const float* bo = (const float*)d_in[8];
    float* out = (float*)d_out;

    __half *x16, *wpk, *QKV, *Ah, *P;
    float *bqkv, *zg;
    cudaGetSymbolAddress((void**)&x16, g_x16);
    cudaGetSymbolAddress((void**)&wpk, g_w);
    cudaGetSymbolAddress((void**)&bqkv, g_bqkv);
    cudaGetSymbolAddress((void**)&QKV, g_QKV);
    cudaGetSymbolAddress((void**)&Ah, g_Ah);
    cudaGetSymbolAddress((void**)&zg, g_z);
    cudaGetSymbolAddress((void**)&P, g_P);

    cudaFuncSetAttribute(zpass, cudaFuncAttributeMaxDynamicSharedMemorySize, Z_SMEM);
    cudaFuncSetAttribute(ppass, cudaFuncAttributeMaxDynamicSharedMemorySize, P_SMEM);
    cudaFuncSetAttribute(pv16,  cudaFuncAttributeMaxDynamicSharedMemorySize, PV_SMEM);

    cvt_all<<<2048, 256>>>(x, Wq, Wk, Wv, Wo, bq, bk, bv, x16, wpk, bqkv);

    dim3 gqkv(3 * DIM / 64, SEQ / 128);
    qkv16<<<gqkv, 256>>>(x16, wpk, bqkv, QKV);

    const __half* Qh = QKV;
    const __half* Kh = QKV + (size_t)SEQ * DIM;
    const __half* Vh = QKV + (size_t)2 * SEQ * DIM;

    dim3 gsp(SEQ / 64, SEQ / 128);
    zpass<<<gsp, 512, Z_SMEM>>>(Qh, Kh, zg);
    ppass<<<gsp, 512, P_SMEM>>>(Qh, Kh, zg, P);

    dim3 gpv(1, SEQ / 128, NHEAD);
    pv16<<<gpv, 256, PV_SMEM>>>(P, Vh, Ah);

    dim3 glin(DIM / 64, SEQ / 128);
    oproj16<<<glin, 256>>>(Ah, wpk + (size_t)3 * DIM * DIM, bo, out);
}

// round 7
// speedup vs baseline: 1.1966x; 1.1966x over previous
#include <cuda_runtime.h>
#include <cuda_fp16.h>
#include <cstdint>

#define SEQ 4096
#define DIM 768
#define NHEAD 12
#define DHEAD 64
#define POST_SCALE 19.595917942265423f  // sqrt(384)

// ---- device scratch (allocation-free rule) ----
__device__ __half g_x16[SEQ * DIM];
__device__ __half g_w[4 * DIM * DIM];          // packed Wq,Wk,Wv,Wo (fp16)
__device__ float  g_bqkv[3 * DIM];             // packed bq,bk,bv
__device__ __half g_QKV[3 * SEQ * DIM];        // Q,K,V planes (fp16)
__device__ __half g_Ah[SEQ * DIM];
__device__ __half g_P[(size_t)NHEAD * SEQ * SEQ];  // 402 MB

// ---------------- PTX helpers ----------------
__device__ __forceinline__ void cp16(uint32_t dst, const void* src) {
    asm volatile("cp.async.cg.shared.global [%0], [%1], 16;\n" :: "r"(dst), "l"(src));
}
#define CP_COMMIT() asm volatile("cp.async.commit_group;\n")
#define CP_WAIT0()  asm volatile("cp.async.wait_group 0;\n")
#define CP_WAIT1()  asm volatile("cp.async.wait_group 1;\n")
#define CP_WAIT2()  asm volatile("cp.async.wait_group 2;\n")

#define LDSM4(R, a) asm volatile( \
    "ldmatrix.sync.aligned.m8n8.x4.shared.b16 {%0,%1,%2,%3}, [%4];" \
    : "=r"((R)[0]), "=r"((R)[1]), "=r"((R)[2]), "=r"((R)[3]) : "r"(a))
#define LDSM4T(R, a) asm volatile( \
    "ldmatrix.sync.aligned.m8n8.x4.trans.shared.b16 {%0,%1,%2,%3}, [%4];" \
    : "=r"((R)[0]), "=r"((R)[1]), "=r"((R)[2]), "=r"((R)[3]) : "r"(a))

__device__ __forceinline__ void mma16(float* c, const uint32_t* a, const uint32_t* b) {
    asm volatile(
        "mma.sync.aligned.m16n8k16.row.col.f32.f16.f16.f32 "
        "{%0,%1,%2,%3},{%4,%5,%6,%7},{%8,%9},{%0,%1,%2,%3};\n"
        : "+f"(c[0]), "+f"(c[1]), "+f"(c[2]), "+f"(c[3])
        : "r"(a[0]), "r"(a[1]), "r"(a[2]), "r"(a[3]), "r"(b[0]), "r"(b[1]));
}

// swizzled byte offset within a tile of 128B rows (8x16B chunks, chunk ^= row&7)
__device__ __forceinline__ uint32_t swz(int row, int ch) {
    return (uint32_t)(row * 128 + ((ch ^ (row & 7)) << 4));
}

// ---------------- merged fp32 -> fp16 convert + packing ----------------
#define NX2 (SEQ * DIM / 2)
#define NW2 (DIM * DIM / 2)
__global__ void cvt_all(
    const float* __restrict__ x,
    const float* __restrict__ Wq, const float* __restrict__ Wk,
    const float* __restrict__ Wv, const float* __restrict__ Wo,
    const float* __restrict__ bq, const float* __restrict__ bk,
    const float* __restrict__ bv,
    __half* __restrict__ x16, __half* __restrict__ wpk,
    float* __restrict__ bqkv)
{
    int i = blockIdx.x * blockDim.x + threadIdx.x;
    int stride = gridDim.x * blockDim.x;
    if (i < 3 * DIM) {
        bqkv[i] = (i < DIM) ? bq[i] : (i < 2 * DIM ? bk[i - DIM] : bv[i - 2 * DIM]);
    }
    __half2* xd = (__half2*)x16;
    __half2* wd = (__half2*)wpk;
    for (int j = i; j < NX2 + 4 * NW2; j += stride) {
        float2 v;
        if (j < NX2) {
            v = ((const float2*)x)[j];
            xd[j] = __floats2half2_rn(v.x, v.y);
        } else {
            int k = j - NX2;
            int seg = k / NW2, off = k - seg * NW2;
            const float* W = (seg == 0) ? Wq : (seg == 1) ? Wk : (seg == 2) ? Wv : Wo;
            v = ((const float2*)W)[off];
            wd[k] = __floats2half2_rn(v.x, v.y);
        }
    }
}

// ============================================================
// QKV fused: Y[plane][4096,768] = X @ Wpk[n,:]^T + bqkv.
// N = 2304 over packed weights. BM=128 BN=64 BK=64, 256 thr.
// ============================================================
__global__ __launch_bounds__(256) void qkv16(
    const __half* __restrict__ X, const __half* __restrict__ W,
    const float* __restrict__ bias, __half* __restrict__ QKV)
{
    __shared__ __align__(16) unsigned char smbuf[49152];
    const uint32_t smb = (uint32_t)__cvta_generic_to_shared(smbuf);
    const int tid = threadIdx.x, lane = tid & 31, warp = tid >> 5;
    const int wm = warp >> 1, wn = warp & 1;
    const int m0 = blockIdx.y * 128, n0 = blockIdx.x * 64;
    const int g = lane >> 2, t4 = lane & 3;
    const int plane = n0 / DIM, ncol = n0 - plane * DIM;
    __half* Y = QKV + (size_t)plane * SEQ * DIM;

    float c[2][4][4];
#pragma unroll
    for (int mt = 0; mt < 2; mt++)
#pragma unroll
        for (int nt = 0; nt < 4; nt++)
#pragma unroll
            for (int r = 0; r < 4; r++) c[mt][nt][r] = 0.f;

    {
        uint32_t ab = smb, bb = smb + 16384;
#pragma unroll
        for (int i = 0; i < 4; i++) {
            int op = tid + i * 256; int row = op >> 3, ch = op & 7;
            cp16(ab + swz(row, ch), X + (size_t)(m0 + row) * DIM + ch * 8);
        }
#pragma unroll
        for (int i = 0; i < 2; i++) {
            int op = tid + i * 256; int row = op >> 3, ch = op & 7;
            cp16(bb + swz(row, ch), W + (size_t)(n0 + row) * DIM + ch * 8);
        }
        CP_COMMIT();
    }

    for (int it = 0; it < 12; it++) {
        if (it < 11) {
            int kt = (it + 1) * 64;
            uint32_t ab = smb + ((it + 1) & 1) * 24576, bb = ab + 16384;
#pragma unroll
            for (int i = 0; i < 4; i++) {
                int op = tid + i * 256; int row = op >> 3, ch = op & 7;
                cp16(ab + swz(row, ch), X + (size_t)(m0 + row) * DIM + kt + ch * 8);
            }
#pragma unroll
            for (int i = 0; i < 2; i++) {
                int op = tid + i * 256; int row = op >> 3, ch = op & 7;
                cp16(bb + swz(row, ch), W + (size_t)(n0 + row) * DIM + kt + ch * 8);
            }
            CP_COMMIT();
            CP_WAIT1();
        } else {
            CP_WAIT0();
        }
        __syncthreads();

        uint32_t ab = smb + (it & 1) * 24576, bb = ab + 16384;
#pragma unroll
        for (int ks = 0; ks < 4; ks++) {
            uint32_t a[2][4], b[2][4];
#pragma unroll
            for (int mt = 0; mt < 2; mt++) {
                int row = wm * 32 + mt * 16 + (lane & 15);
                int ch = ks * 2 + (lane >> 4);
                LDSM4(a[mt], ab + swz(row, ch));
            }
#pragma unroll
            for (int p = 0; p < 2; p++) {
                int row = wn * 32 + p * 16 + (lane & 7) + ((lane >> 4) << 3);
                int ch = ks * 2 + ((lane >> 3) & 1);
                LDSM4(b[p], bb + swz(row, ch));
            }
#pragma unroll
            for (int mt = 0; mt < 2; mt++) {
                mma16(c[mt][0], a[mt], &b[0][0]);
                mma16(c[mt][1], a[mt], &b[0][2]);
                mma16(c[mt][2], a[mt], &b[1][0]);
                mma16(c[mt][3], a[mt], &b[1][2]);
            }
        }
        __syncthreads();
    }

#pragma unroll
    for (int mt = 0; mt < 2; mt++)
#pragma unroll
        for (int nt = 0; nt < 4; nt++) {
            int cg = n0 + wn * 32 + nt * 8 + t4 * 2;
            float b0 = bias[cg], b1 = bias[cg + 1];
            int col = ncol + wn * 32 + nt * 8 + t4 * 2;
#pragma unroll
            for (int rh = 0; rh < 2; rh++) {
                int row = m0 + wm * 32 + mt * 16 + g + rh * 8;
                *(__half2*)(Y + (size_t)row * DIM + col) =
                    __floats2half2_rn(c[mt][nt][rh * 2] + b0, c[mt][nt][rh * 2 + 1] + b1);
            }
        }
}

// ============================================================
// Final linear: out[4096,768] fp32 = A @ Wo^T + bo.
// ============================================================
__global__ __launch_bounds__(256) void oproj16(
    const __half* __restrict__ X, const __half* __restrict__ W,
    const float* __restrict__ bias, float* __restrict__ Y)
{
    __shared__ __align__(16) unsigned char smbuf[49152];
    const uint32_t smb = (uint32_t)__cvta_generic_to_shared(smbuf);
    const int tid = threadIdx.x, lane = tid & 31, warp = tid >> 5;
    const int wm = warp >> 1, wn = warp & 1;
    const int m0 = blockIdx.y * 128, n0 = blockIdx.x * 64;
    const int g = lane >> 2, t4 = lane & 3;

    float c[2][4][4];
#pragma unroll
    for (int mt = 0; mt < 2; mt++)
#pragma unroll
        for (int nt = 0; nt < 4; nt++)
#pragma unroll
            for (int r = 0; r < 4; r++) c[mt][nt][r] = 0.f;

    {
        uint32_t ab = smb, bb = smb + 16384;
#pragma unroll
        for (int i = 0; i < 4; i++) {
            int op = tid + i * 256; int row = op >> 3, ch = op & 7;
            cp16(ab + swz(row, ch), X + (size_t)(m0 + row) * DIM + ch * 8);
        }
#pragma unroll
        for (int i = 0; i < 2; i++) {
            int op = tid + i * 256; int row = op >> 3, ch = op & 7;
            cp16(bb + swz(row, ch), W + (size_t)(n0 + row) * DIM + ch * 8);
        }
        CP_COMMIT();
    }

    for (int it = 0; it < 12; it++) {
        if (it < 11) {
            int kt = (it + 1) * 64;
            uint32_t ab = smb + ((it + 1) & 1) * 24576, bb = ab + 16384;
#pragma unroll
            for (int i = 0; i < 4; i++) {
                int op = tid + i * 256; int row = op >> 3, ch = op & 7;
                cp16(ab + swz(row, ch), X + (size_t)(m0 + row) * DIM + kt + ch * 8);
            }
#pragma unroll
            for (int i = 0; i < 2; i++) {
                int op = tid + i * 256; int row = op >> 3, ch = op & 7;
                cp16(bb + swz(row, ch), W + (size_t)(n0 + row) * DIM + kt + ch * 8);
            }
            CP_COMMIT();
            CP_WAIT1();
        } else {
            CP_WAIT0();
        }
        __syncthreads();

        uint32_t ab = smb + (it & 1) * 24576, bb = ab + 16384;
#pragma unroll
        for (int ks = 0; ks < 4; ks++) {
            uint32_t a[2][4], b[2][4];
#pragma unroll
            for (int mt = 0; mt < 2; mt++) {
                int row = wm * 32 + mt * 16 + (lane & 15);
                int ch = ks * 2 + (lane >> 4);
                LDSM4(a[mt], ab + swz(row, ch));
            }
#pragma unroll
            for (int p = 0; p < 2; p++) {
                int row = wn * 32 + p * 16 + (lane & 7) + ((lane >> 4) << 3);
                int ch = ks * 2 + ((lane >> 3) & 1);
                LDSM4(b[p], bb + swz(row, ch));
            }
#pragma unroll
            for (int mt = 0; mt < 2; mt++) {
                mma16(c[mt][0], a[mt], &b[0][0]);
                mma16(c[mt][1], a[mt], &b[0][2]);
                mma16(c[mt][2], a[mt], &b[1][0]);
                mma16(c[mt][3], a[mt], &b[1][2]);
            }
        }
        __syncthreads();
    }

#pragma unroll
    for (int mt = 0; mt < 2; mt++)
#pragma unroll
        for (int nt = 0; nt < 4; nt++) {
            int col = n0 + wn * 32 + nt * 8 + t4 * 2;
            float b0 = bias[col], b1 = bias[col + 1];
#pragma unroll
            for (int rh = 0; rh < 2; rh++) {
                int row = m0 + wm * 32 + mt * 16 + g + rh * 8;
                float2 v = {c[mt][nt][rh * 2] + b0, c[mt][nt][rh * 2 + 1] + b1};
                *(float2*)(Y + (size_t)row * DIM + col) = v;
            }
        }
}

// ============================================================
// Scores + head-softmax (Round-3 proven version).
// CTA tile 64(s) x 64(t), 512 threads, 16 warps (4s x 4t),
// warp tile m16 x n16. Scores staged in smem fp32
// (12 x 64 x 64, row-xor swizzle), softmax over h,
// coalesced half2 P stores.
// ============================================================
#define SC_BYTES  (12 * 64 * 64 * 4)   // 196608
#define STG_OFF   SC_BYTES
#define SC_SMEM   (SC_BYTES + 2 * 16384)  // 229376

__global__ __launch_bounds__(512) void scores16(
    const __half* __restrict__ Qh, const __half* __restrict__ Kh,
    __half* __restrict__ P)
{
    extern __shared__ __align__(16) unsigned char sm[];
    float* sc = (float*)sm;
    const uint32_t smb = (uint32_t)__cvta_generic_to_shared(sm);
    const uint32_t stg = smb + STG_OFF;
    const int tid = threadIdx.x, lane = tid & 31, warp = tid >> 5;
    const int wm = warp >> 2, wn = warp & 3;
    const int s0 = blockIdx.y * 64, t0 = blockIdx.x * 64;
    const int g = lane >> 2, t4 = lane & 3;
    const int row8 = tid >> 3, ch8 = tid & 7;

    // prologue: head 0 K (8KB) + Q (8KB) into buf 0
    cp16(stg + swz(row8, ch8), Kh + (size_t)(s0 + row8) * DIM + ch8 * 8);
    cp16(stg + 8192 + swz(row8, ch8), Qh + (size_t)(t0 + row8) * DIM + ch8 * 8);
    CP_COMMIT();

#pragma unroll
    for (int h = 0; h < NHEAD; h++) {
        if (h < NHEAD - 1) {
            uint32_t base = stg + ((h + 1) & 1) * 16384;
            int hc = (h + 1) * DHEAD;
            cp16(base + swz(row8, ch8), Kh + (size_t)(s0 + row8) * DIM + hc + ch8 * 8);
            cp16(base + 8192 + swz(row8, ch8), Qh + (size_t)(t0 + row8) * DIM + hc + ch8 * 8);
            CP_COMMIT();
            CP_WAIT1();
        } else {
            CP_WAIT0();
        }
        __syncthreads();

        uint32_t kb = stg + (h & 1) * 16384, qb = kb + 8192;
        float acc[2][4];
#pragma unroll
        for (int nt = 0; nt < 2; nt++)
#pragma unroll
            for (int r = 0; r < 4; r++) acc[nt][r] = 0.f;

#pragma unroll
        for (int ks = 0; ks < 4; ks++) {
            uint32_t a[4], b[4];
            {
                int row = wm * 16 + (lane & 15);
                int ch = ks * 2 + (lane >> 4);
                LDSM4(a, kb + swz(row, ch));
            }
            {
                int row = wn * 16 + (lane & 7) + ((lane >> 4) << 3);
                int ch = ks * 2 + ((lane >> 3) & 1);
                LDSM4(b, qb + swz(row, ch));
            }
            mma16(acc[0], a, &b[0]);
            mma16(acc[1], a, &b[2]);
        }

        // store scores (float2, row-xor swizzle keeps pairs adjacent)
#pragma unroll
        for (int nt = 0; nt < 2; nt++)
#pragma unroll
            for (int rh = 0; rh < 2; rh++) {
                int r = wm * 16 + g + rh * 8;
                int col = wn * 16 + nt * 8 + t4 * 2;
                float2 v = {acc[nt][rh * 2], acc[nt][rh * 2 + 1]};
                *(float2*)&sc[h * 4096 + r * 64 + (col ^ ((r & 7) << 3))] = v;
            }
        __syncthreads();
    }

    // softmax over heads per (s, t-pair); coalesced half2 P stores
#pragma unroll
    for (int i = 0; i < 4; i++) {
        int p = tid + i * 512;           // 2048 pairs
        int s = p >> 5, tp = p & 31;
        int base = s * 64 + ((2 * tp) ^ ((s & 7) << 3));
        float ex[NHEAD], ey[NHEAD];
        float zx = 0.f, zy = 0.f;
#pragma unroll
        for (int h = 0; h < NHEAD; h++) {
            float2 v = *(const float2*)&sc[h * 4096 + base];
            ex[h] = __expf(v.x); ey[h] = __expf(v.y);
            zx += ex[h]; zy += ey[h];
        }
        float ix = POST_SCALE / zx, iy = POST_SCALE / zy;
#pragma unroll
        for (int h = 0; h < NHEAD; h++) {
            *(__half2*)(P + ((size_t)h * SEQ + s0 + s) * SEQ + t0 + 2 * tp) =
                __floats2half2_rn(ex[h] * ix, ey[h] * iy);
        }
    }
}

// ============================================================
// PV (Round-5 proven version): out[s,h*64+d] = sum_t P V.
// BM=128, BN=64, BK=64, 3-stage cp.async ring, 256 threads.
// ============================================================
#define PV_STAGE 24576    // 16KB A + 8KB B per stage
#define PV_SMEM  (3 * PV_STAGE)

__global__ __launch_bounds__(256) void pv16(
    const __half* __restrict__ P, const __half* __restrict__ V,
    __half* __restrict__ Y)
{
    extern __shared__ __align__(16) unsigned char pvsm[];
    const uint32_t smb = (uint32_t)__cvta_generic_to_shared(pvsm);
    const int tid = threadIdx.x, lane = tid & 31, warp = tid >> 5;
    const int wm = warp >> 1, wn = warp & 1;
    const int h = blockIdx.z;
    const int m0 = blockIdx.y * 128;
    const int g = lane >> 2, t4 = lane & 3;
    const __half* Ph = P + (size_t)h * SEQ * SEQ;

    float c[2][4][4];
#pragma unroll
    for (int mt = 0; mt < 2; mt++)
#pragma unroll
        for (int nt = 0; nt < 4; nt++)
#pragma unroll
            for (int r = 0; r < 4; r++) c[mt][nt][r] = 0.f;

#pragma unroll
    for (int st = 0; st < 2; st++) {
        int kt = st * 64;
        uint32_t ab = smb + st * PV_STAGE, bb = ab + 16384;
#pragma unroll
        for (int i = 0; i < 4; i++) {
            int op = tid + i * 256; int row = op >> 3, ch = op & 7;
            cp16(ab + swz(row, ch), Ph + (size_t)(m0 + row) * SEQ + kt + ch * 8);
        }
#pragma unroll
        for (int i = 0; i < 2; i++) {
            int op = tid + i * 256; int row = op >> 3, ch = op & 7;
            cp16(bb + swz(row, ch), V + (size_t)(kt + row) * DIM + h * DHEAD + ch * 8);
        }
        CP_COMMIT();
    }

    for (int it = 0; it < 64; it++) {
        int left = 63 - it;
        if (left >= 2) {
            int kt = (it + 2) * 64;
            uint32_t ab = smb + ((it + 2) % 3) * PV_STAGE, bb = ab + 16384;
#pragma unroll
            for (int i = 0; i < 4; i++) {
                int op = tid + i * 256; int row = op >> 3, ch = op & 7;
                cp16(ab + swz(row, ch), Ph + (size_t)(m0 + row) * SEQ + kt + ch * 8);
            }
#pragma unroll
            for (int i = 0; i < 2; i++) {
                int op = tid + i * 256; int row = op >> 3, ch = op & 7;
                cp16(bb + swz(row, ch), V + (size_t)(kt + row) * DIM + h * DHEAD + ch * 8);
            }
            CP_COMMIT();
            CP_WAIT2();
        } else if (left == 1) {
            CP_WAIT1();
        } else {
            CP_WAIT0();
        }
        __syncthreads();

        uint32_t ab = smb + (it % 3) * PV_STAGE, bb = ab + 16384;
#pragma unroll
        for (int ks = 0; ks < 4; ks++) {
            uint32_t a[2][4], b[2][4];
#pragma unroll
            for (int mt = 0; mt < 2; mt++) {
                int row = wm * 32 + mt * 16 + (lane & 15);
                int ch = ks * 2 + (lane >> 4);
                LDSM4(a[mt], ab + swz(row, ch));
            }
#pragma unroll
            for (int p = 0; p < 2; p++) {
                int row = ks * 16 + (lane & 15);
                int ch = wn * 4 + p * 2 + (lane >> 4);
                LDSM4T(b[p], bb + swz(row, ch));
            }
#pragma unroll
            for (int mt = 0; mt < 2; mt++) {
                mma16(c[mt][0], a[mt], &b[0][0]);
                mma16(c[mt][1], a[mt], &b[0][2]);
                mma16(c[mt][2], a[mt], &b[1][0]);
                mma16(c[mt][3], a[mt], &b[1][2]);
            }
        }
        __syncthreads();
    }

#pragma unroll
    for (int mt = 0; mt < 2; mt++)
#pragma unroll
        for (int nt = 0; nt < 4; nt++) {
            int col = h * DHEAD + wn * 32 + nt * 8 + t4 * 2;
#pragma unroll
            for (int rh = 0; rh < 2; rh++) {
                int row = m0 + wm * 32 + mt * 16 + g + rh * 8;
                *(__half2*)(Y + (size_t)row * DIM + col) =
                    __floats2half2_rn(c[mt][nt][rh * 2], c[mt][nt][rh * 2 + 1]);
            }
        }
}

// ============================================================
extern "C" void kernel_launch(void* const* d_in, const int* in_sizes, int n_in,
                              void* d_out, int out_size)
{
    const float* x  = (const float*)d_in[0];
    const float* Wq = (const float*)d_in[1];
    const float* bq = (const float*)d_in[2];
    const float* Wk = (const float*)d_in[3];
    const float* bk = (const float*)d_in[4];
    const float* Wv = (const float*)d_in[5];
    const float* bv = (const float*)d_in[6];
    const float* Wo = (const float*)d_in[7];
    const float* bo = (const float*)d_in[8];
    float* out = (float*)d_out;

    __half *x16, *wpk, *QKV, *Ah, *P;
    float* bqkv;
    cudaGetSymbolAddress((void**)&x16, g_x16);
    cudaGetSymbolAddress((void**)&wpk, g_w);
    cudaGetSymbolAddress((void**)&bqkv, g_bqkv);
    cudaGetSymbolAddress((void**)&QKV, g_QKV);
    cudaGetSymbolAddress((void**)&Ah, g_Ah);
    cudaGetSymbolAddress((void**)&P, g_P);

    cudaFuncSetAttribute(scores16, cudaFuncAttributeMaxDynamicSharedMemorySize, SC_SMEM);
    cudaFuncSetAttribute(pv16,     cudaFuncAttributeMaxDynamicSharedMemorySize, PV_SMEM);

    cvt_all<<<2048, 256>>>(x, Wq, Wk, Wv, Wo, bq, bk, bv, x16, wpk, bqkv);

    dim3 gqkv(3 * DIM / 64, SEQ / 128);
    qkv16<<<gqkv, 256>>>(x16, wpk, bqkv, QKV);

    const __half* Qh = QKV;
    const __half* Kh = QKV + (size_t)SEQ * DIM;
    const __half* Vh = QKV + (size_t)2 * SEQ * DIM;

    dim3 gsc(SEQ / 64, SEQ / 64);
    scores16<<<gsc, 512, SC_SMEM>>>(Qh, Kh, P);

    dim3 gpv(1, SEQ / 128, NHEAD);
    pv16<<<gpv, 256, PV_SMEM>>>(P, Vh, Ah);

    dim3 glin(DIM / 64, SEQ / 128);
    oproj16<<<glin, 256>>>(Ah, wpk + (size_t)3 * DIM * DIM, bo, out);
}

// round 10
// speedup vs baseline: 1.2121x; 1.0129x over previous
#include <cuda_runtime.h>
#include <cuda_fp16.h>
#include <cstdint>

#define SEQ 4096
#define DIM 768
#define NHEAD 12
#define DHEAD 64
#define POST_SCALE 19.595917942265423f  // sqrt(384)

// ---- device scratch (allocation-free rule) ----
__device__ __half g_x16[SEQ * DIM];
__device__ __half g_w[4 * DIM * DIM];          // packed Wq,Wk,Wv,Wo (fp16)
__device__ float  g_bqkv[3 * DIM];             // packed bq,bk,bv
__device__ __half g_QKV[3 * SEQ * DIM];        // Q,K,V planes (fp16)
__device__ __half g_Ah[SEQ * DIM];
__device__ __half g_P[(size_t)NHEAD * SEQ * SEQ];  // 402 MB

// ---------------- PTX helpers ----------------
__device__ __forceinline__ void cp16(uint32_t dst, const void* src) {
    asm volatile("cp.async.cg.shared.global [%0], [%1], 16;\n" :: "r"(dst), "l"(src));
}
#define CP_COMMIT() asm volatile("cp.async.commit_group;\n")
#define CP_WAIT0()  asm volatile("cp.async.wait_group 0;\n")
#define CP_WAIT1()  asm volatile("cp.async.wait_group 1;\n")
#define CP_WAIT2()  asm volatile("cp.async.wait_group 2;\n")

#define LDSM4(R, a) asm volatile( \
    "ldmatrix.sync.aligned.m8n8.x4.shared.b16 {%0,%1,%2,%3}, [%4];" \
    : "=r"((R)[0]), "=r"((R)[1]), "=r"((R)[2]), "=r"((R)[3]) : "r"(a))
#define LDSM4T(R, a) asm volatile( \
    "ldmatrix.sync.aligned.m8n8.x4.trans.shared.b16 {%0,%1,%2,%3}, [%4];" \
    : "=r"((R)[0]), "=r"((R)[1]), "=r"((R)[2]), "=r"((R)[3]) : "r"(a))

__device__ __forceinline__ void mma16(float* c, const uint32_t* a, const uint32_t* b) {
    asm volatile(
        "mma.sync.aligned.m16n8k16.row.col.f32.f16.f16.f32 "
        "{%0,%1,%2,%3},{%4,%5,%6,%7},{%8,%9},{%0,%1,%2,%3};\n"
        : "+f"(c[0]), "+f"(c[1]), "+f"(c[2]), "+f"(c[3])
        : "r"(a[0]), "r"(a[1]), "r"(a[2]), "r"(a[3]), "r"(b[0]), "r"(b[1]));
}

// swizzled byte offset within a tile of 128B rows (8x16B chunks, chunk ^= row&7)
__device__ __forceinline__ uint32_t swz(int row, int ch) {
    return (uint32_t)(row * 128 + ((ch ^ (row & 7)) << 4));
}

// ---------------- merged fp32 -> fp16 convert + packing ----------------
#define NX2 (SEQ * DIM / 2)
#define NW2 (DIM * DIM / 2)
__global__ void cvt_all(
    const float* __restrict__ x,
    const float* __restrict__ Wq, const float* __restrict__ Wk,
    const float* __restrict__ Wv, const float* __restrict__ Wo,
    const float* __restrict__ bq, const float* __restrict__ bk,
    const float* __restrict__ bv,
    __half* __restrict__ x16, __half* __restrict__ wpk,
    float* __restrict__ bqkv)
{
    int i = blockIdx.x * blockDim.x + threadIdx.x;
    int stride = gridDim.x * blockDim.x;
    if (i < 3 * DIM) {
        bqkv[i] = (i < DIM) ? bq[i] : (i < 2 * DIM ? bk[i - DIM] : bv[i - 2 * DIM]);
    }
    __half2* xd = (__half2*)x16;
    __half2* wd = (__half2*)wpk;
    for (int j = i; j < NX2 + 4 * NW2; j += stride) {
        float2 v;
        if (j < NX2) {
            v = ((const float2*)x)[j];
            xd[j] = __floats2half2_rn(v.x, v.y);
        } else {
            int k = j - NX2;
            int seg = k / NW2, off = k - seg * NW2;
            const float* W = (seg == 0) ? Wq : (seg == 1) ? Wk : (seg == 2) ? Wv : Wo;
            v = ((const float2*)W)[off];
            wd[k] = __floats2half2_rn(v.x, v.y);
        }
    }
}

// ============================================================
// QKV fused (unchanged, proven): Y = X @ Wpk^T + bqkv.
// ============================================================
__global__ __launch_bounds__(256) void qkv16(
    const __half* __restrict__ X, const __half* __restrict__ W,
    const float* __restrict__ bias, __half* __restrict__ QKV)
{
    __shared__ __align__(16) unsigned char smbuf[49152];
    const uint32_t smb = (uint32_t)__cvta_generic_to_shared(smbuf);
    const int tid = threadIdx.x, lane = tid & 31, warp = tid >> 5;
    const int wm = warp >> 1, wn = warp & 1;
    const int m0 = blockIdx.y * 128, n0 = blockIdx.x * 64;
    const int g = lane >> 2, t4 = lane & 3;
    const int plane = n0 / DIM, ncol = n0 - plane * DIM;
    __half* Y = QKV + (size_t)plane * SEQ * DIM;

    float c[2][4][4];
#pragma unroll
    for (int mt = 0; mt < 2; mt++)
#pragma unroll
        for (int nt = 0; nt < 4; nt++)
#pragma unroll
            for (int r = 0; r < 4; r++) c[mt][nt][r] = 0.f;

    {
        uint32_t ab = smb, bb = smb + 16384;
#pragma unroll
        for (int i = 0; i < 4; i++) {
            int op = tid + i * 256; int row = op >> 3, ch = op & 7;
            cp16(ab + swz(row, ch), X + (size_t)(m0 + row) * DIM + ch * 8);
        }
#pragma unroll
        for (int i = 0; i < 2; i++) {
            int op = tid + i * 256; int row = op >> 3, ch = op & 7;
            cp16(bb + swz(row, ch), W + (size_t)(n0 + row) * DIM + ch * 8);
        }
        CP_COMMIT();
    }

    for (int it = 0; it < 12; it++) {
        if (it < 11) {
            int kt = (it + 1) * 64;
            uint32_t ab = smb + ((it + 1) & 1) * 24576, bb = ab + 16384;
#pragma unroll
            for (int i = 0; i < 4; i++) {
                int op = tid + i * 256; int row = op >> 3, ch = op & 7;
                cp16(ab + swz(row, ch), X + (size_t)(m0 + row) * DIM + kt + ch * 8);
            }
#pragma unroll
            for (int i = 0; i < 2; i++) {
                int op = tid + i * 256; int row = op >> 3, ch = op & 7;
                cp16(bb + swz(row, ch), W + (size_t)(n0 + row) * DIM + kt + ch * 8);
            }
            CP_COMMIT();
            CP_WAIT1();
        } else {
            CP_WAIT0();
        }
        __syncthreads();

        uint32_t ab = smb + (it & 1) * 24576, bb = ab + 16384;
#pragma unroll
        for (int ks = 0; ks < 4; ks++) {
            uint32_t a[2][4], b[2][4];
#pragma unroll
            for (int mt = 0; mt < 2; mt++) {
                int row = wm * 32 + mt * 16 + (lane & 15);
                int ch = ks * 2 + (lane >> 4);
                LDSM4(a[mt], ab + swz(row, ch));
            }
#pragma unroll
            for (int p = 0; p < 2; p++) {
                int row = wn * 32 + p * 16 + (lane & 7) + ((lane >> 4) << 3);
                int ch = ks * 2 + ((lane >> 3) & 1);
                LDSM4(b[p], bb + swz(row, ch));
            }
#pragma unroll
            for (int mt = 0; mt < 2; mt++) {
                mma16(c[mt][0], a[mt], &b[0][0]);
                mma16(c[mt][1], a[mt], &b[0][2]);
                mma16(c[mt][2], a[mt], &b[1][0]);
                mma16(c[mt][3], a[mt], &b[1][2]);
            }
        }
        __syncthreads();
    }

#pragma unroll
    for (int mt = 0; mt < 2; mt++)
#pragma unroll
        for (int nt = 0; nt < 4; nt++) {
            int cg = n0 + wn * 32 + nt * 8 + t4 * 2;
            float b0 = bias[cg], b1 = bias[cg + 1];
            int col = ncol + wn * 32 + nt * 8 + t4 * 2;
#pragma unroll
            for (int rh = 0; rh < 2; rh++) {
                int row = m0 + wm * 32 + mt * 16 + g + rh * 8;
                *(__half2*)(Y + (size_t)row * DIM + col) =
                    __floats2half2_rn(c[mt][nt][rh * 2] + b0, c[mt][nt][rh * 2 + 1] + b1);
            }
        }
}

// ============================================================
// Final linear (unchanged): out fp32 = A @ Wo^T + bo.
// ============================================================
__global__ __launch_bounds__(256) void oproj16(
    const __half* __restrict__ X, const __half* __restrict__ W,
    const float* __restrict__ bias, float* __restrict__ Y)
{
    __shared__ __align__(16) unsigned char smbuf[49152];
    const uint32_t smb = (uint32_t)__cvta_generic_to_shared(smbuf);
    const int tid = threadIdx.x, lane = tid & 31, warp = tid >> 5;
    const int wm = warp >> 1, wn = warp & 1;
    const int m0 = blockIdx.y * 128, n0 = blockIdx.x * 64;
    const int g = lane >> 2, t4 = lane & 3;

    float c[2][4][4];
#pragma unroll
    for (int mt = 0; mt < 2; mt++)
#pragma unroll
        for (int nt = 0; nt < 4; nt++)
#pragma unroll
            for (int r = 0; r < 4; r++) c[mt][nt][r] = 0.f;

    {
        uint32_t ab = smb, bb = smb + 16384;
#pragma unroll
        for (int i = 0; i < 4; i++) {
            int op = tid + i * 256; int row = op >> 3, ch = op & 7;
            cp16(ab + swz(row, ch), X + (size_t)(m0 + row) * DIM + ch * 8);
        }
#pragma unroll
        for (int i = 0; i < 2; i++) {
            int op = tid + i * 256; int row = op >> 3, ch = op & 7;
            cp16(bb + swz(row, ch), W + (size_t)(n0 + row) * DIM + ch * 8);
        }
        CP_COMMIT();
    }

    for (int it = 0; it < 12; it++) {
        if (it < 11) {
            int kt = (it + 1) * 64;
            uint32_t ab = smb + ((it + 1) & 1) * 24576, bb = ab + 16384;
#pragma unroll
            for (int i = 0; i < 4; i++) {
                int op = tid + i * 256; int row = op >> 3, ch = op & 7;
                cp16(ab + swz(row, ch), X + (size_t)(m0 + row) * DIM + kt + ch * 8);
            }
#pragma unroll
            for (int i = 0; i < 2; i++) {
                int op = tid + i * 256; int row = op >> 3, ch = op & 7;
                cp16(bb + swz(row, ch), W + (size_t)(n0 + row) * DIM + kt + ch * 8);
            }
            CP_COMMIT();
            CP_WAIT1();
        } else {
            CP_WAIT0();
        }
        __syncthreads();

        uint32_t ab = smb + (it & 1) * 24576, bb = ab + 16384;
#pragma unroll
        for (int ks = 0; ks < 4; ks++) {
            uint32_t a[2][4], b[2][4];
#pragma unroll
            for (int mt = 0; mt < 2; mt++) {
                int row = wm * 32 + mt * 16 + (lane & 15);
                int ch = ks * 2 + (lane >> 4);
                LDSM4(a[mt], ab + swz(row, ch));
            }
#pragma unroll
            for (int p = 0; p < 2; p++) {
                int row = wn * 32 + p * 16 + (lane & 7) + ((lane >> 4) << 3);
                int ch = ks * 2 + ((lane >> 3) & 1);
                LDSM4(b[p], bb + swz(row, ch));
            }
#pragma unroll
            for (int mt = 0; mt < 2; mt++) {
                mma16(c[mt][0], a[mt], &b[0][0]);
                mma16(c[mt][1], a[mt], &b[0][2]);
                mma16(c[mt][2], a[mt], &b[1][0]);
                mma16(c[mt][3], a[mt], &b[1][2]);
            }
        }
        __syncthreads();
    }

#pragma unroll
    for (int mt = 0; mt < 2; mt++)
#pragma unroll
        for (int nt = 0; nt < 4; nt++) {
            int col = n0 + wn * 32 + nt * 8 + t4 * 2;
            float b0 = bias[col], b1 = bias[col + 1];
#pragma unroll
            for (int rh = 0; rh < 2; rh++) {
                int row = m0 + wm * 32 + mt * 16 + g + rh * 8;
                float2 v = {c[mt][nt][rh * 2] + b0, c[mt][nt][rh * 2 + 1] + b1};
                *(float2*)(Y + (size_t)row * DIM + col) = v;
            }
        }
}

// ============================================================
// Scores + head-softmax. CTA tile 64(s) x 64(t), 512 threads,
// 16 warps (4s x 4t), warp tile m16 x n16.
// CHANGE vs R7: exp(score) computed at store time (overlaps
// MUFU with next head's cp.async/mma) — smem holds exp values;
// tail softmax is just sum + scale + store.
// ============================================================
#define SC_BYTES  (12 * 64 * 64 * 4)   // 196608
#define STG_OFF   SC_BYTES
#define SC_SMEM   (SC_BYTES + 2 * 16384)  // 229376

__global__ __launch_bounds__(512) void scores16(
    const __half* __restrict__ Qh, const __half* __restrict__ Kh,
    __half* __restrict__ P)
{
    extern __shared__ __align__(16) unsigned char sm[];
    float* sc = (float*)sm;
    const uint32_t smb = (uint32_t)__cvta_generic_to_shared(sm);
    const uint32_t stg = smb + STG_OFF;
    const int tid = threadIdx.x, lane = tid & 31, warp = tid >> 5;
    const int wm = warp >> 2, wn = warp & 3;
    const int s0 = blockIdx.y * 64, t0 = blockIdx.x * 64;
    const int g = lane >> 2, t4 = lane & 3;
    const int row8 = tid >> 3, ch8 = tid & 7;

    // prologue: head 0 K (8KB) + Q (8KB) into buf 0
    cp16(stg + swz(row8, ch8), Kh + (size_t)(s0 + row8) * DIM + ch8 * 8);
    cp16(stg + 8192 + swz(row8, ch8), Qh + (size_t)(t0 + row8) * DIM + ch8 * 8);
    CP_COMMIT();

#pragma unroll
    for (int h = 0; h < NHEAD; h++) {
        if (h < NHEAD - 1) {
            uint32_t base = stg + ((h + 1) & 1) * 16384;
            int hc = (h + 1) * DHEAD;
            cp16(base + swz(row8, ch8), Kh + (size_t)(s0 + row8) * DIM + hc + ch8 * 8);
            cp16(base + 8192 + swz(row8, ch8), Qh + (size_t)(t0 + row8) * DIM + hc + ch8 * 8);
            CP_COMMIT();
            CP_WAIT1();
        } else {
            CP_WAIT0();
        }
        __syncthreads();

        uint32_t kb = stg + (h & 1) * 16384, qb = kb + 8192;
        float acc[2][4];
#pragma unroll
        for (int nt = 0; nt < 2; nt++)
#pragma unroll
            for (int r = 0; r < 4; r++) acc[nt][r] = 0.f;

#pragma unroll
        for (int ks = 0; ks < 4; ks++) {
            uint32_t a[4], b[4];
            {
                int row = wm * 16 + (lane & 15);
                int ch = ks * 2 + (lane >> 4);
                LDSM4(a, kb + swz(row, ch));
            }
            {
                int row = wn * 16 + (lane & 7) + ((lane >> 4) << 3);
                int ch = ks * 2 + ((lane >> 3) & 1);
                LDSM4(b, qb + swz(row, ch));
            }
            mma16(acc[0], a, &b[0]);
            mma16(acc[1], a, &b[2]);
        }

        // store exp(score) — MUFU work overlaps next head's pipeline
#pragma unroll
        for (int nt = 0; nt < 2; nt++)
#pragma unroll
            for (int rh = 0; rh < 2; rh++) {
                int r = wm * 16 + g + rh * 8;
                int col = wn * 16 + nt * 8 + t4 * 2;
                float2 v = {__expf(acc[nt][rh * 2]), __expf(acc[nt][rh * 2 + 1])};
                *(float2*)&sc[h * 4096 + r * 64 + (col ^ ((r & 7) << 3))] = v;
            }
        __syncthreads();
    }

    // softmax tail: sum 12 exps per (s, t-pair), scale, store
#pragma unroll
    for (int i = 0; i < 4; i++) {
        int p = tid + i * 512;           // 2048 pairs
        int s = p >> 5, tp = p & 31;
        int base = s * 64 + ((2 * tp) ^ ((s & 7) << 3));
        float ex[NHEAD], ey[NHEAD];
        float zx = 0.f, zy = 0.f;
#pragma unroll
        for (int h = 0; h < NHEAD; h++) {
            float2 v = *(const float2*)&sc[h * 4096 + base];
            ex[h] = v.x; ey[h] = v.y;
            zx += v.x; zy += v.y;
        }
        float ix = POST_SCALE / zx, iy = POST_SCALE / zy;
#pragma unroll
        for (int h = 0; h < NHEAD; h++) {
            *(__half2*)(P + ((size_t)h * SEQ + s0 + s) * SEQ + t0 + 2 * tp) =
                __floats2half2_rn(ex[h] * ix, ey[h] * iy);
        }
    }
}

// ============================================================
// PV (R5-proven + 3-CTA residency hint): BM=128, BN=64, BK=64,
// 3-stage cp.async ring, 256 threads.
// ============================================================
#define PV_STAGE 24576
#define PV_SMEM  (3 * PV_STAGE)

__global__ __launch_bounds__(256, 3) void pv16(
    const __half* __restrict__ P, const __half* __restrict__ V,
    __half* __restrict__ Y)
{
    extern __shared__ __align__(16) unsigned char pvsm[];
    const uint32_t smb = (uint32_t)__cvta_generic_to_shared(pvsm);
    const int tid = threadIdx.x, lane = tid & 31, warp = tid >> 5;
    const int wm = warp >> 1, wn = warp & 1;
    const int h = blockIdx.z;
    const int m0 = blockIdx.y * 128;
    const int g = lane >> 2, t4 = lane & 3;
    const __half* Ph = P + (size_t)h * SEQ * SEQ;

    float c[2][4][4];
#pragma unroll
    for (int mt = 0; mt < 2; mt++)
#pragma unroll
        for (int nt = 0; nt < 4; nt++)
#pragma unroll
            for (int r = 0; r < 4; r++) c[mt][nt][r] = 0.f;

#pragma unroll
    for (int st = 0; st < 2; st++) {
        int kt = st * 64;
        uint32_t ab = smb + st * PV_STAGE, bb = ab + 16384;
#pragma unroll
        for (int i = 0; i < 4; i++) {
            int op = tid + i * 256; int row = op >> 3, ch = op & 7;
            cp16(ab + swz(row, ch), Ph + (size_t)(m0 + row) * SEQ + kt + ch * 8);
        }
#pragma unroll
        for (int i = 0; i < 2; i++) {
            int op = tid + i * 256; int row = op >> 3, ch = op & 7;
            cp16(bb + swz(row, ch), V + (size_t)(kt + row) * DIM + h * DHEAD + ch * 8);
        }
        CP_COMMIT();
    }

    for (int it = 0; it < 64; it++) {
        int left = 63 - it;
        if (left >= 2) {
            int kt = (it + 2) * 64;
            uint32_t ab = smb + ((it + 2) % 3) * PV_STAGE, bb = ab + 16384;
#pragma unroll
            for (int i = 0; i < 4; i++) {
                int op = tid + i * 256; int row = op >> 3, ch = op & 7;
                cp16(ab + swz(row, ch), Ph + (size_t)(m0 + row) * SEQ + kt + ch * 8);
            }
#pragma unroll
            for (int i = 0; i < 2; i++) {
                int op = tid + i * 256; int row = op >> 3, ch = op & 7;
                cp16(bb + swz(row, ch), V + (size_t)(kt + row) * DIM + h * DHEAD + ch * 8);
            }
            CP_COMMIT();
            CP_WAIT2();
        } else if (left == 1) {
            CP_WAIT1();
        } else {
            CP_WAIT0();
        }
        __syncthreads();

        uint32_t ab = smb + (it % 3) * PV_STAGE, bb = ab + 16384;
#pragma unroll
        for (int ks = 0; ks < 4; ks++) {
            uint32_t a[2][4], b[2][4];
#pragma unroll
            for (int mt = 0; mt < 2; mt++) {
                int row = wm * 32 + mt * 16 + (lane & 15);
                int ch = ks * 2 + (lane >> 4);
                LDSM4(a[mt], ab + swz(row, ch));
            }
#pragma unroll
            for (int p = 0; p < 2; p++) {
                int row = ks * 16 + (lane & 15);
                int ch = wn * 4 + p * 2 + (lane >> 4);
                LDSM4T(b[p], bb + swz(row, ch));
            }
#pragma unroll
            for (int mt = 0; mt < 2; mt++) {
                mma16(c[mt][0], a[mt], &b[0][0]);
                mma16(c[mt][1], a[mt], &b[0][2]);
                mma16(c[mt][2], a[mt], &b[1][0]);
                mma16(c[mt][3], a[mt], &b[1][2]);
            }
        }
        __syncthreads();
    }

#pragma unroll
    for (int mt = 0; mt < 2; mt++)
#pragma unroll
        for (int nt = 0; nt < 4; nt++) {
            int col = h * DHEAD + wn * 32 + nt * 8 + t4 * 2;
#pragma unroll
            for (int rh = 0; rh < 2; rh++) {
                int row = m0 + wm * 32 + mt * 16 + g + rh * 8;
                *(__half2*)(Y + (size_t)row * DIM + col) =
                    __floats2half2_rn(c[mt][nt][rh * 2], c[mt][nt][rh * 2 + 1]);
            }
        }
}

// ============================================================
extern "C" void kernel_launch(void* const* d_in, const int* in_sizes, int n_in,
                              void* d_out, int out_size)
{
    const float* x  = (const float*)d_in[0];
    const float* Wq = (const float*)d_in[1];
    const float* bq = (const float*)d_in[2];
    const float* Wk = (const float*)d_in[3];
    const float* bk = (const float*)d_in[4];
    const float* Wv = (const float*)d_in[5];
    const float* bv = (const float*)d_in[6];
    const float* Wo = (const float*)d_in[7];
    const float* bo = (const float*)d_in[8];
    float* out = (float*)d_out;

    __half *x16, *wpk, *QKV, *Ah, *P;
    float* bqkv;
    cudaGetSymbolAddress((void**)&x16, g_x16);
    cudaGetSymbolAddress((void**)&wpk, g_w);
    cudaGetSymbolAddress((void**)&bqkv, g_bqkv);
    cudaGetSymbolAddress((void**)&QKV, g_QKV);
    cudaGetSymbolAddress((void**)&Ah, g_Ah);
    cudaGetSymbolAddress((void**)&P, g_P);

    cudaFuncSetAttribute(scores16, cudaFuncAttributeMaxDynamicSharedMemorySize, SC_SMEM);
    cudaFuncSetAttribute(pv16,     cudaFuncAttributeMaxDynamicSharedMemorySize, PV_SMEM);

    cvt_all<<<2048, 256>>>(x, Wq, Wk, Wv, Wo, bq, bk, bv, x16, wpk, bqkv);

    dim3 gqkv(3 * DIM / 64, SEQ / 128);
    qkv16<<<gqkv, 256>>>(x16, wpk, bqkv, QKV);

    const __half* Qh = QKV;
    const __half* Kh = QKV + (size_t)SEQ * DIM;
    const __half* Vh = QKV + (size_t)2 * SEQ * DIM;

    dim3 gsc(SEQ / 64, SEQ / 64);
    scores16<<<gsc, 512, SC_SMEM>>>(Qh, Kh, P);

    dim3 gpv(1, SEQ / 128, NHEAD);
    pv16<<<gpv, 256, PV_SMEM>>>(P, Vh, Ah);

    dim3 glin(DIM / 64, SEQ / 128);
    oproj16<<<glin, 256>>>(Ah, wpk + (size_t)3 * DIM * DIM, bo, out);
}

// round 11
// speedup vs baseline: 1.3936x; 1.1497x over previous
#include <cuda_runtime.h>
#include <cuda_fp16.h>
#include <cstdint>

#define SEQ 4096
#define DIM 768
#define NHEAD 12
#define DHEAD 64
#define POST_SCALE 19.595917942265423f  // sqrt(384)
#define EXP_OFS 8.0f                    // exp(s-8): cancels in softmax, avoids fp16 overflow

// ---- device scratch (allocation-free rule) ----
__device__ __half g_x16[SEQ * DIM];
__device__ __half g_w[4 * DIM * DIM];          // packed Wq,Wk,Wv,Wo (fp16)
__device__ float  g_bqkv[3 * DIM];             // packed bq,bk,bv
__device__ __half g_QKV[3 * SEQ * DIM];        // Q,K,V planes (fp16)
__device__ __half g_Ah[SEQ * DIM];
__device__ __half g_P[(size_t)NHEAD * SEQ * SEQ];  // 402 MB

// ---------------- PTX helpers ----------------
__device__ __forceinline__ void cp16(uint32_t dst, const void* src) {
    asm volatile("cp.async.cg.shared.global [%0], [%1], 16;\n" :: "r"(dst), "l"(src));
}
#define CP_COMMIT() asm volatile("cp.async.commit_group;\n")
#define CP_WAIT0()  asm volatile("cp.async.wait_group 0;\n")
#define CP_WAIT1()  asm volatile("cp.async.wait_group 1;\n")
#define CP_WAIT2()  asm volatile("cp.async.wait_group 2;\n")

#define LDSM4(R, a) asm volatile( \
    "ldmatrix.sync.aligned.m8n8.x4.shared.b16 {%0,%1,%2,%3}, [%4];" \
    : "=r"((R)[0]), "=r"((R)[1]), "=r"((R)[2]), "=r"((R)[3]) : "r"(a))
#define LDSM4T(R, a) asm volatile( \
    "ldmatrix.sync.aligned.m8n8.x4.trans.shared.b16 {%0,%1,%2,%3}, [%4];" \
    : "=r"((R)[0]), "=r"((R)[1]), "=r"((R)[2]), "=r"((R)[3]) : "r"(a))

__device__ __forceinline__ void mma16(float* c, const uint32_t* a, const uint32_t* b) {
    asm volatile(
        "mma.sync.aligned.m16n8k16.row.col.f32.f16.f16.f32 "
        "{%0,%1,%2,%3},{%4,%5,%6,%7},{%8,%9},{%0,%1,%2,%3};\n"
        : "+f"(c[0]), "+f"(c[1]), "+f"(c[2]), "+f"(c[3])
        : "r"(a[0]), "r"(a[1]), "r"(a[2]), "r"(a[3]), "r"(b[0]), "r"(b[1]));
}

// swizzled byte offset within a tile of 128B rows (8x16B chunks, chunk ^= row&7)
__device__ __forceinline__ uint32_t swz(int row, int ch) {
    return (uint32_t)(row * 128 + ((ch ^ (row & 7)) << 4));
}

// ---------------- merged fp32 -> fp16 convert + packing ----------------
#define NX2 (SEQ * DIM / 2)
#define NW2 (DIM * DIM / 2)
__global__ void cvt_all(
    const float* __restrict__ x,
    const float* __restrict__ Wq, const float* __restrict__ Wk,
    const float* __restrict__ Wv, const float* __restrict__ Wo,
    const float* __restrict__ bq, const float* __restrict__ bk,
    const float* __restrict__ bv,
    __half* __restrict__ x16, __half* __restrict__ wpk,
    float* __restrict__ bqkv)
{
    int i = blockIdx.x * blockDim.x + threadIdx.x;
    int stride = gridDim.x * blockDim.x;
    if (i < 3 * DIM) {
        bqkv[i] = (i < DIM) ? bq[i] : (i < 2 * DIM ? bk[i - DIM] : bv[i - 2 * DIM]);
    }
    __half2* xd = (__half2*)x16;
    __half2* wd = (__half2*)wpk;
    for (int j = i; j < NX2 + 4 * NW2; j += stride) {
        float2 v;
        if (j < NX2) {
            v = ((const float2*)x)[j];
            xd[j] = __floats2half2_rn(v.x, v.y);
        } else {
            int k = j - NX2;
            int seg = k / NW2, off = k - seg * NW2;
            const float* W = (seg == 0) ? Wq : (seg == 1) ? Wk : (seg == 2) ? Wv : Wo;
            v = ((const float2*)W)[off];
            wd[k] = __floats2half2_rn(v.x, v.y);
        }
    }
}

// ============================================================
// QKV fused (unchanged, proven): Y = X @ Wpk^T + bqkv.
// ============================================================
__global__ __launch_bounds__(256) void qkv16(
    const __half* __restrict__ X, const __half* __restrict__ W,
    const float* __restrict__ bias, __half* __restrict__ QKV)
{
    __shared__ __align__(16) unsigned char smbuf[49152];
    const uint32_t smb = (uint32_t)__cvta_generic_to_shared(smbuf);
    const int tid = threadIdx.x, lane = tid & 31, warp = tid >> 5;
    const int wm = warp >> 1, wn = warp & 1;
    const int m0 = blockIdx.y * 128, n0 = blockIdx.x * 64;
    const int g = lane >> 2, t4 = lane & 3;
    const int plane = n0 / DIM, ncol = n0 - plane * DIM;
    __half* Y = QKV + (size_t)plane * SEQ * DIM;

    float c[2][4][4];
#pragma unroll
    for (int mt = 0; mt < 2; mt++)
#pragma unroll
        for (int nt = 0; nt < 4; nt++)
#pragma unroll
            for (int r = 0; r < 4; r++) c[mt][nt][r] = 0.f;

    {
        uint32_t ab = smb, bb = smb + 16384;
#pragma unroll
        for (int i = 0; i < 4; i++) {
            int op = tid + i * 256; int row = op >> 3, ch = op & 7;
            cp16(ab + swz(row, ch), X + (size_t)(m0 + row) * DIM + ch * 8);
        }
#pragma unroll
        for (int i = 0; i < 2; i++) {
            int op = tid + i * 256; int row = op >> 3, ch = op & 7;
            cp16(bb + swz(row, ch), W + (size_t)(n0 + row) * DIM + ch * 8);
        }
        CP_COMMIT();
    }

    for (int it = 0; it < 12; it++) {
        if (it < 11) {
            int kt = (it + 1) * 64;
            uint32_t ab = smb + ((it + 1) & 1) * 24576, bb = ab + 16384;
#pragma unroll
            for (int i = 0; i < 4; i++) {
                int op = tid + i * 256; int row = op >> 3, ch = op & 7;
                cp16(ab + swz(row, ch), X + (size_t)(m0 + row) * DIM + kt + ch * 8);
            }
#pragma unroll
            for (int i = 0; i < 2; i++) {
                int op = tid + i * 256; int row = op >> 3, ch = op & 7;
                cp16(bb + swz(row, ch), W + (size_t)(n0 + row) * DIM + kt + ch * 8);
            }
            CP_COMMIT();
            CP_WAIT1();
        } else {
            CP_WAIT0();
        }
        __syncthreads();

        uint32_t ab = smb + (it & 1) * 24576, bb = ab + 16384;
#pragma unroll
        for (int ks = 0; ks < 4; ks++) {
            uint32_t a[2][4], b[2][4];
#pragma unroll
            for (int mt = 0; mt < 2; mt++) {
                int row = wm * 32 + mt * 16 + (lane & 15);
                int ch = ks * 2 + (lane >> 4);
                LDSM4(a[mt], ab + swz(row, ch));
            }
#pragma unroll
            for (int p = 0; p < 2; p++) {
                int row = wn * 32 + p * 16 + (lane & 7) + ((lane >> 4) << 3);
                int ch = ks * 2 + ((lane >> 3) & 1);
                LDSM4(b[p], bb + swz(row, ch));
            }
#pragma unroll
            for (int mt = 0; mt < 2; mt++) {
                mma16(c[mt][0], a[mt], &b[0][0]);
                mma16(c[mt][1], a[mt], &b[0][2]);
                mma16(c[mt][2], a[mt], &b[1][0]);
                mma16(c[mt][3], a[mt], &b[1][2]);
            }
        }
        __syncthreads();
    }

#pragma unroll
    for (int mt = 0; mt < 2; mt++)
#pragma unroll
        for (int nt = 0; nt < 4; nt++) {
            int cg = n0 + wn * 32 + nt * 8 + t4 * 2;
            float b0 = bias[cg], b1 = bias[cg + 1];
            int col = ncol + wn * 32 + nt * 8 + t4 * 2;
#pragma unroll
            for (int rh = 0; rh < 2; rh++) {
                int row = m0 + wm * 32 + mt * 16 + g + rh * 8;
                *(__half2*)(Y + (size_t)row * DIM + col) =
                    __floats2half2_rn(c[mt][nt][rh * 2] + b0, c[mt][nt][rh * 2 + 1] + b1);
            }
        }
}

// ============================================================
// Final linear (unchanged): out fp32 = A @ Wo^T + bo.
// ============================================================
__global__ __launch_bounds__(256) void oproj16(
    const __half* __restrict__ X, const __half* __restrict__ W,
    const float* __restrict__ bias, float* __restrict__ Y)
{
    __shared__ __align__(16) unsigned char smbuf[49152];
    const uint32_t smb = (uint32_t)__cvta_generic_to_shared(smbuf);
    const int tid = threadIdx.x, lane = tid & 31, warp = tid >> 5;
    const int wm = warp >> 1, wn = warp & 1;
    const int m0 = blockIdx.y * 128, n0 = blockIdx.x * 64;
    const int g = lane >> 2, t4 = lane & 3;

    float c[2][4][4];
#pragma unroll
    for (int mt = 0; mt < 2; mt++)
#pragma unroll
        for (int nt = 0; nt < 4; nt++)
#pragma unroll
            for (int r = 0; r < 4; r++) c[mt][nt][r] = 0.f;

    {
        uint32_t ab = smb, bb = smb + 16384;
#pragma unroll
        for (int i = 0; i < 4; i++) {
            int op = tid + i * 256; int row = op >> 3, ch = op & 7;
            cp16(ab + swz(row, ch), X + (size_t)(m0 + row) * DIM + ch * 8);
        }
#pragma unroll
        for (int i = 0; i < 2; i++) {
            int op = tid + i * 256; int row = op >> 3, ch = op & 7;
            cp16(bb + swz(row, ch), W + (size_t)(n0 + row) * DIM + ch * 8);
        }
        CP_COMMIT();
    }

    for (int it = 0; it < 12; it++) {
        if (it < 11) {
            int kt = (it + 1) * 64;
            uint32_t ab = smb + ((it + 1) & 1) * 24576, bb = ab + 16384;
#pragma unroll
            for (int i = 0; i < 4; i++) {
                int op = tid + i * 256; int row = op >> 3, ch = op & 7;
                cp16(ab + swz(row, ch), X + (size_t)(m0 + row) * DIM + kt + ch * 8);
            }
#pragma unroll
            for (int i = 0; i < 2; i++) {
                int op = tid + i * 256; int row = op >> 3, ch = op & 7;
                cp16(bb + swz(row, ch), W + (size_t)(n0 + row) * DIM + kt + ch * 8);
            }
            CP_COMMIT();
            CP_WAIT1();
        } else {
            CP_WAIT0();
        }
        __syncthreads();

        uint32_t ab = smb + (it & 1) * 24576, bb = ab + 16384;
#pragma unroll
        for (int ks = 0; ks < 4; ks++) {
            uint32_t a[2][4], b[2][4];
#pragma unroll
            for (int mt = 0; mt < 2; mt++) {
                int row = wm * 32 + mt * 16 + (lane & 15);
                int ch = ks * 2 + (lane >> 4);
                LDSM4(a[mt], ab + swz(row, ch));
            }
#pragma unroll
            for (int p = 0; p < 2; p++) {
                int row = wn * 32 + p * 16 + (lane & 7) + ((lane >> 4) << 3);
                int ch = ks * 2 + ((lane >> 3) & 1);
                LDSM4(b[p], bb + swz(row, ch));
            }
#pragma unroll
            for (int mt = 0; mt < 2; mt++) {
                mma16(c[mt][0], a[mt], &b[0][0]);
                mma16(c[mt][1], a[mt], &b[0][2]);
                mma16(c[mt][2], a[mt], &b[1][0]);
                mma16(c[mt][3], a[mt], &b[1][2]);
            }
        }
        __syncthreads();
    }

#pragma unroll
    for (int mt = 0; mt < 2; mt++)
#pragma unroll
        for (int nt = 0; nt < 4; nt++) {
            int col = n0 + wn * 32 + nt * 8 + t4 * 2;
            float b0 = bias[col], b1 = bias[col + 1];
#pragma unroll
            for (int rh = 0; rh < 2; rh++) {
                int row = m0 + wm * 32 + mt * 16 + g + rh * 8;
                float2 v = {c[mt][nt][rh * 2] + b0, c[mt][nt][rh * 2 + 1] + b1};
                *(float2*)(Y + (size_t)row * DIM + col) = v;
            }
        }
}

// ============================================================
// Scores + head-softmax, restructured:
// CTA tile 64(s) x 64(t), 512 threads = 4 head-groups x 4 warps.
// Each group: warp tile m32 x n32 (2x2 warps) -> operand LDSM
// redundancy 2x (was 4x). 3 stages x 4 concurrent heads,
// 64KB/stage double-buffered. Scores stored as fp16 exp(s-8)
// (98KB); offset cancels in softmax. ~6 syncs total (was 24).
// ============================================================
#define SC_BYTES  (12 * 64 * 64 * 2)      // 98304 fp16 exp-scores
#define STG_OFF   SC_BYTES
#define SC_SMEM   (SC_BYTES + 2 * 65536)  // 229376

__global__ __launch_bounds__(512) void scores16(
    const __half* __restrict__ Qh, const __half* __restrict__ Kh,
    __half* __restrict__ P)
{
    extern __shared__ __align__(16) unsigned char sm[];
    __half* sc = (__half*)sm;
    const uint32_t smb = (uint32_t)__cvta_generic_to_shared(sm);
    const uint32_t stg = smb + STG_OFF;
    const int tid = threadIdx.x, lane = tid & 31, warp = tid >> 5;
    const int grp = warp >> 2;                 // head group 0..3
    const int ws = (warp >> 1) & 1, wt = warp & 1;  // 2x2 within group
    const int s0 = blockIdx.y * 64, t0 = blockIdx.x * 64;
    const int g = lane >> 2, t4 = lane & 3;

    // stage loader: heads st*4+j, j=0..3. Per head: K 64x64 (8KB) + Q 64x64 (8KB).
#define LOAD_ST(st) do {                                                          \
        uint32_t buf = stg + ((st) & 1) * 65536;                                  \
        _Pragma("unroll")                                                         \
        for (int i = 0; i < 8; i++) {                                             \
            int op = tid + i * 512;                                               \
            int j = op >> 10, r = op & 1023;                                      \
            int hc = ((st) * 4 + j) * DHEAD;                                      \
            if (r < 512) {                                                        \
                int row = r >> 3, ch = r & 7;                                     \
                cp16(buf + j * 16384 + swz(row, ch),                              \
                     Kh + (size_t)(s0 + row) * DIM + hc + ch * 8);                \
            } else {                                                              \
                int r2 = r - 512; int row = r2 >> 3, ch = r2 & 7;                 \
                cp16(buf + j * 16384 + 8192 + swz(row, ch),                       \
                     Qh + (size_t)(t0 + row) * DIM + hc + ch * 8);                \
            }                                                                     \
        }                                                                         \
        CP_COMMIT();                                                              \
    } while (0)

#define COMPUTE_ST(st) do {                                                       \
        uint32_t kb = stg + ((st) & 1) * 65536 + grp * 16384;                     \
        uint32_t qb = kb + 8192;                                                  \
        int h = (st) * 4 + grp;                                                   \
        float acc[2][4][4];                                                       \
        _Pragma("unroll")                                                         \
        for (int mt = 0; mt < 2; mt++)                                            \
            _Pragma("unroll")                                                     \
            for (int nt = 0; nt < 4; nt++)                                        \
                _Pragma("unroll")                                                 \
                for (int r = 0; r < 4; r++) acc[mt][nt][r] = 0.f;                 \
        _Pragma("unroll")                                                         \
        for (int ks = 0; ks < 4; ks++) {                                          \
            uint32_t a[2][4], b[2][4];                                            \
            _Pragma("unroll")                                                     \
            for (int mt = 0; mt < 2; mt++) {                                      \
                int row = ws * 32 + mt * 16 + (lane & 15);                        \
                int ch = ks * 2 + (lane >> 4);                                    \
                LDSM4(a[mt], kb + swz(row, ch));                                  \
            }                                                                     \
            _Pragma("unroll")                                                     \
            for (int p = 0; p < 2; p++) {                                         \
                int row = wt * 32 + p * 16 + (lane & 7) + ((lane >> 4) << 3);     \
                int ch = ks * 2 + ((lane >> 3) & 1);                              \
                LDSM4(b[p], qb + swz(row, ch));                                   \
            }                                                                     \
            _Pragma("unroll")                                                     \
            for (int mt = 0; mt < 2; mt++) {                                      \
                mma16(acc[mt][0], a[mt], &b[0][0]);                               \
                mma16(acc[mt][1], a[mt], &b[0][2]);                               \
                mma16(acc[mt][2], a[mt], &b[1][0]);                               \
                mma16(acc[mt][3], a[mt], &b[1][2]);                               \
            }                                                                     \
        }                                                                         \
        _Pragma("unroll")                                                         \
        for (int mt = 0; mt < 2; mt++)                                            \
            _Pragma("unroll")                                                     \
            for (int nt = 0; nt < 4; nt++)                                        \
                _Pragma("unroll")                                                 \
                for (int rh = 0; rh < 2; rh++) {                                  \
                    int r = ws * 32 + mt * 16 + g + rh * 8;                       \
                    int col = wt * 32 + nt * 8 + t4 * 2;                          \
                    __half2 e = __floats2half2_rn(                                \
                        __expf(acc[mt][nt][rh * 2] - EXP_OFS),                    \
                        __expf(acc[mt][nt][rh * 2 + 1] - EXP_OFS));               \
                    *(__half2*)&sc[h * 4096 + r * 64 + (col ^ ((r & 7) << 3))] = e;\
                }                                                                 \
    } while (0)

    LOAD_ST(0);
    LOAD_ST(1);

    CP_WAIT1();
    __syncthreads();
    COMPUTE_ST(0);
    __syncthreads();           // buf0 consumed -> safe to refill
    LOAD_ST(2);

    CP_WAIT1();
    __syncthreads();
    COMPUTE_ST(1);

    CP_WAIT0();
    __syncthreads();
    COMPUTE_ST(2);
    __syncthreads();

    // softmax tail: sum 12 fp16 exps per (s, t-pair), scale, store
#pragma unroll
    for (int i = 0; i < 4; i++) {
        int p = tid + i * 512;           // 2048 pairs
        int s = p >> 5, tp = p & 31;
        int base = s * 64 + ((2 * tp) ^ ((s & 7) << 3));
        float ex[NHEAD], ey[NHEAD];
        float zx = 0.f, zy = 0.f;
#pragma unroll
        for (int h = 0; h < NHEAD; h++) {
            float2 v = __half22float2(*(const __half2*)&sc[h * 4096 + base]);
            ex[h] = v.x; ey[h] = v.y;
            zx += v.x; zy += v.y;
        }
        float ix = POST_SCALE / zx, iy = POST_SCALE / zy;
#pragma unroll
        for (int h = 0; h < NHEAD; h++) {
            *(__half2*)(P + ((size_t)h * SEQ + s0 + s) * SEQ + t0 + 2 * tp) =
                __floats2half2_rn(ex[h] * ix, ey[h] * iy);
        }
    }
#undef LOAD_ST
#undef COMPUTE_ST
}

// ============================================================
// PV (unchanged from R10, measured 84.4us): BM=128, BN=64,
// BK=64, 3-stage cp.async ring, 256 threads, 3 CTAs/SM hint.
// ============================================================
#define PV_STAGE 24576
#define PV_SMEM  (3 * PV_STAGE)

__global__ __launch_bounds__(256, 3) void pv16(
    const __half* __restrict__ P, const __half* __restrict__ V,
    __half* __restrict__ Y)
{
    extern __shared__ __align__(16) unsigned char pvsm[];
    const uint32_t smb = (uint32_t)__cvta_generic_to_shared(pvsm);
    const int tid = threadIdx.x, lane = tid & 31, warp = tid >> 5;
    const int wm = warp >> 1, wn = warp & 1;
    const int h = blockIdx.z;
    const int m0 = blockIdx.y * 128;
    const int g = lane >> 2, t4 = lane & 3;
    const __half* Ph = P + (size_t)h * SEQ * SEQ;

    float c[2][4][4];
#pragma unroll
    for (int mt = 0; mt < 2; mt++)
#pragma unroll
        for (int nt = 0; nt < 4; nt++)
#pragma unroll
            for (int r = 0; r < 4; r++) c[mt][nt][r] = 0.f;

#pragma unroll
    for (int st = 0; st < 2; st++) {
        int kt = st * 64;
        uint32_t ab = smb + st * PV_STAGE, bb = ab + 16384;
#pragma unroll
        for (int i = 0; i < 4; i++) {
            int op = tid + i * 256; int row = op >> 3, ch = op & 7;
            cp16(ab + swz(row, ch), Ph + (size_t)(m0 + row) * SEQ + kt + ch * 8);
        }
#pragma unroll
        for (int i = 0; i < 2; i++) {
            int op = tid + i * 256; int row = op >> 3, ch = op & 7;
            cp16(bb + swz(row, ch), V + (size_t)(kt + row) * DIM + h * DHEAD + ch * 8);
        }
        CP_COMMIT();
    }

    for (int it = 0; it < 64; it++) {
        int left = 63 - it;
        if (left >= 2) {
            int kt = (it + 2) * 64;
            uint32_t ab = smb + ((it + 2) % 3) * PV_STAGE, bb = ab + 16384;
#pragma unroll
            for (int i = 0; i < 4; i++) {
                int op = tid + i * 256; int row = op >> 3, ch = op & 7;
                cp16(ab + swz(row, ch), Ph + (size_t)(m0 + row) * SEQ + kt + ch * 8);
            }
#pragma unroll
            for (int i = 0; i < 2; i++) {
                int op = tid + i * 256; int row = op >> 3, ch = op & 7;
                cp16(bb + swz(row, ch), V + (size_t)(kt + row) * DIM + h * DHEAD + ch * 8);
            }
            CP_COMMIT();
            CP_WAIT2();
        } else if (left == 1) {
            CP_WAIT1();
        } else {
            CP_WAIT0();
        }
        __syncthreads();

        uint32_t ab = smb + (it % 3) * PV_STAGE, bb = ab + 16384;
#pragma unroll
        for (int ks = 0; ks < 4; ks++) {
            uint32_t a[2][4], b[2][4];
#pragma unroll
            for (int mt = 0; mt < 2; mt++) {
                int row = wm * 32 + mt * 16 + (lane & 15);
                int ch = ks * 2 + (lane >> 4);
                LDSM4(a[mt], ab + swz(row, ch));
            }
#pragma unroll
            for (int p = 0; p < 2; p++) {
                int row = ks * 16 + (lane & 15);
                int ch = wn * 4 + p * 2 + (lane >> 4);
                LDSM4T(b[p], bb + swz(row, ch));
            }
#pragma unroll
            for (int mt = 0; mt < 2; mt++) {
                mma16(c[mt][0], a[mt], &b[0][0]);
                mma16(c[mt][1], a[mt], &b[0][2]);
                mma16(c[mt][2], a[mt], &b[1][0]);
                mma16(c[mt][3], a[mt], &b[1][2]);
            }
        }
        __syncthreads();
    }

#pragma unroll
    for (int mt = 0; mt < 2; mt++)
#pragma unroll
        for (int nt = 0; nt < 4; nt++) {
            int col = h * DHEAD + wn * 32 + nt * 8 + t4 * 2;
#pragma unroll
            for (int rh = 0; rh < 2; rh++) {
                int row = m0 + wm * 32 + mt * 16 + g + rh * 8;
                *(__half2*)(Y + (size_t)row * DIM + col) =
                    __floats2half2_rn(c[mt][nt][rh * 2], c[mt][nt][rh * 2 + 1]);
            }
        }
}

// ============================================================
extern "C" void kernel_launch(void* const* d_in, const int* in_sizes, int n_in,
                              void* d_out, int out_size)
{
    const float* x  = (const float*)d_in[0];
    const float* Wq = (const float*)d_in[1];
    const float* bq = (const float*)d_in[2];
    const float* Wk = (const float*)d_in[3];
    const float* bk = (const float*)d_in[4];
    const float* Wv = (const float*)d_in[5];
    const float* bv = (const float*)d_in[6];
    const float* Wo = (const float*)d_in[7];
    const float* bo = (const float*)d_in[8];
    float* out = (float*)d_out;

    __half *x16, *wpk, *QKV, *Ah, *P;
    float* bqkv;
    cudaGetSymbolAddress((void**)&x16, g_x16);
    cudaGetSymbolAddress((void**)&wpk, g_w);
    cudaGetSymbolAddress((void**)&bqkv, g_bqkv);
    cudaGetSymbolAddress((void**)&QKV, g_QKV);
    cudaGetSymbolAddress((void**)&Ah, g_Ah);
    cudaGetSymbolAddress((void**)&P, g_P);

    cudaFuncSetAttribute(scores16, cudaFuncAttributeMaxDynamicSharedMemorySize, SC_SMEM);
    cudaFuncSetAttribute(pv16,     cudaFuncAttributeMaxDynamicSharedMemorySize, PV_SMEM);

    cvt_all<<<2048, 256>>>(x, Wq, Wk, Wv, Wo, bq, bk, bv, x16, wpk, bqkv);

    dim3 gqkv(3 * DIM / 64, SEQ / 128);
    qkv16<<<gqkv, 256>>>(x16, wpk, bqkv, QKV);

    const __half* Qh = QKV;
    const __half* Kh = QKV + (size_t)SEQ * DIM;
    const __half* Vh = QKV + (size_t)2 * SEQ * DIM;

    dim3 gsc(SEQ / 64, SEQ / 64);
    scores16<<<gsc, 512, SC_SMEM>>>(Qh, Kh, P);

    dim3 gpv(1, SEQ / 128, NHEAD);
    pv16<<<gpv, 256, PV_SMEM>>>(P, Vh, Ah);

    dim3 glin(DIM / 64, SEQ / 128);
    oproj16<<<glin, 256>>>(Ah, wpk + (size_t)3 * DIM * DIM, bo, out);
}